// round 1
// baseline (speedup 1.0000x reference)
#include <cuda_runtime.h>
#include <cuda_bf16.h>
#include <math.h>

// Problem constants
#define Bn 2
#define Tn 2048
#define Cn 1024
#define Hn 16
#define HSn 64
#define FFn 4096
#define EPSn 1e-5f

// ---------------------------------------------------------------------------
// Device scratch (allocations are forbidden; use __device__ globals)
// ---------------------------------------------------------------------------
__device__ float g_Wqt[Cn * Cn];          // [C, H*HS]
__device__ float g_Wkt[Cn * Cn];
__device__ float g_Wvt[Cn * Cn];
__device__ float g_q[Bn * Tn * Cn];       // [B,T,H,HS]
__device__ float g_k[Bn * Tn * Cn];
__device__ float g_v[Bn * Tn * Cn];
__device__ float g_att[Bn * Tn * Cn];     // concat heads [B,T,C]
__device__ float g_t0[Bn * Tn * Cn];      // proj out (pre-LN)
__device__ float g_h[Bn * Tn * Cn];       // LN1 out
__device__ float g_f1[Bn * Tn * FFn];     // FFN mid
__device__ float g_f2[Bn * Tn * Cn];      // FFN out (pre-LN)

// ---------------------------------------------------------------------------
// Weight transpose: W[H,C,HS] -> Wt[C, H*HS]
// ---------------------------------------------------------------------------
__global__ void wtrans_kernel(const float* __restrict__ W, float* __restrict__ Wt) {
    int idx = blockIdx.x * 256 + threadIdx.x;     // over H*C*HS = 1M
    int d = idx & (HSn - 1);
    int c = (idx / HSn) & (Cn - 1);
    int h = idx / (HSn * Cn);
    Wt[(size_t)c * Cn + h * HSn + d] = W[idx];
}

// ---------------------------------------------------------------------------
// Generic SGEMM: C[M,N] = A[M,K] @ B[K,N] + bias[N], optional ReLU.
// 64x64 tile, K-step 16, 256 threads, 4x4 per thread.
// Requires M%64==0, N%64==0, K%16==0 (true for all calls here).
// ---------------------------------------------------------------------------
template <bool RELU>
__global__ void sgemm_kernel(const float* __restrict__ A, const float* __restrict__ B,
                             const float* __restrict__ bias, float* __restrict__ Cout,
                             int M, int N, int K) {
    __shared__ float As[16][68];   // padded, float4-aligned rows
    __shared__ float Bs[16][64];

    int tid = threadIdx.x;
    int m0 = blockIdx.y * 64;
    int n0 = blockIdx.x * 64;
    int ty = tid >> 4;       // 0..15
    int tx = tid & 15;       // 0..15

    float acc[4][4];
#pragma unroll
    for (int i = 0; i < 4; i++)
#pragma unroll
        for (int j = 0; j < 4; j++) acc[i][j] = 0.f;

    for (int k0 = 0; k0 < K; k0 += 16) {
#pragma unroll
        for (int i = 0; i < 4; i++) {
            int idx = tid + i * 256;
            int m = idx >> 4;        // 0..63
            int kk = idx & 15;       // 0..15
            As[kk][m] = A[(size_t)(m0 + m) * K + k0 + kk];
        }
#pragma unroll
        for (int i = 0; i < 4; i++) {
            int idx = tid + i * 256;
            int kk = idx >> 6;       // 0..15
            int n = idx & 63;        // 0..63
            Bs[kk][n] = B[(size_t)(k0 + kk) * N + n0 + n];
        }
        __syncthreads();

#pragma unroll
        for (int kk = 0; kk < 16; kk++) {
            float4 a4 = *(const float4*)&As[kk][ty * 4];
            float4 b4 = *(const float4*)&Bs[kk][tx * 4];
            float a[4] = {a4.x, a4.y, a4.z, a4.w};
            float b[4] = {b4.x, b4.y, b4.z, b4.w};
#pragma unroll
            for (int i = 0; i < 4; i++)
#pragma unroll
                for (int j = 0; j < 4; j++) acc[i][j] = fmaf(a[i], b[j], acc[i][j]);
        }
        __syncthreads();
    }

    float4 bb = *(const float4*)&bias[n0 + tx * 4];
#pragma unroll
    for (int i = 0; i < 4; i++) {
        int m = m0 + ty * 4 + i;
        float4 r;
        r.x = acc[i][0] + bb.x;
        r.y = acc[i][1] + bb.y;
        r.z = acc[i][2] + bb.z;
        r.w = acc[i][3] + bb.w;
        if (RELU) {
            r.x = fmaxf(r.x, 0.f); r.y = fmaxf(r.y, 0.f);
            r.z = fmaxf(r.z, 0.f); r.w = fmaxf(r.w, 0.f);
        }
        *(float4*)&Cout[(size_t)m * N + n0 + tx * 4] = r;
    }
}

// ---------------------------------------------------------------------------
// Causal attention with streaming softmax.
// Q/K/V layout: [B, T, H, HS] (i.e. [B,T,C] with head-contiguous HS blocks).
// One warp per query row; 32 keys per iteration.
// Grid: (T/4, H, B); block: 128 threads (4 warps).
// ---------------------------------------------------------------------------
__global__ void attn_kernel(const float* __restrict__ Q, const float* __restrict__ Kt,
                            const float* __restrict__ V, float* __restrict__ O) {
    int warp = threadIdx.x >> 5;
    int lane = threadIdx.x & 31;
    int t = blockIdx.x * 4 + warp;
    int h = blockIdx.y;
    int b = blockIdx.z;

    __shared__ float sq[4][64];
    const float* qrow = Q + ((size_t)(b * Tn + t)) * Cn + h * HSn;
    sq[warp][lane] = qrow[lane];
    sq[warp][lane + 32] = qrow[lane + 32];
    __syncwarp();
    const float4* sq4 = (const float4*)sq[warp];

    const float* Kbase = Kt + ((size_t)b * Tn) * Cn + h * HSn;
    const float* Vbase = V + ((size_t)b * Tn) * Cn + h * HSn;

    float m = -INFINITY, l = 0.f, o0 = 0.f, o1 = 0.f;
    const float scale = 0.125f;   // HS^-0.5

    for (int s0 = 0; s0 <= t; s0 += 32) {
        int s = s0 + lane;
        bool valid = (s <= t);
        float score = -INFINITY;
        if (valid) {
            const float4* kp = (const float4*)(Kbase + (size_t)s * Cn);
            float acc = 0.f;
#pragma unroll
            for (int i = 0; i < 16; i++) {
                float4 kv = kp[i];
                float4 qv = sq4[i];
                acc = fmaf(kv.x, qv.x, acc);
                acc = fmaf(kv.y, qv.y, acc);
                acc = fmaf(kv.z, qv.z, acc);
                acc = fmaf(kv.w, qv.w, acc);
            }
            score = acc * scale;
        }
        // chunk max
        float mc = score;
#pragma unroll
        for (int off = 16; off; off >>= 1)
            mc = fmaxf(mc, __shfl_xor_sync(0xffffffffu, mc, off));
        float mnew = fmaxf(m, mc);
        float alpha = __expf(m - mnew);             // 0 on first chunk (m=-inf)
        float p = valid ? __expf(score - mnew) : 0.f;
        float ps = p;
#pragma unroll
        for (int off = 16; off; off >>= 1)
            ps += __shfl_xor_sync(0xffffffffu, ps, off);
        l = l * alpha + ps;
        o0 *= alpha;
        o1 *= alpha;

        int lim = t - s0;
        if (lim > 31) lim = 31;
        for (int jj = 0; jj <= lim; jj++) {
            float w = __shfl_sync(0xffffffffu, p, jj);
            const float* vrow = Vbase + (size_t)(s0 + jj) * Cn;
            o0 = fmaf(w, vrow[lane], o0);
            o1 = fmaf(w, vrow[lane + 32], o1);
        }
        m = mnew;
    }

    float inv = 1.f / l;
    float* orow = O + ((size_t)(b * Tn + t)) * Cn + h * HSn;
    orow[lane] = o0 * inv;
    orow[lane + 32] = o1 * inv;
}

// ---------------------------------------------------------------------------
// LayerNorm over last dim (C=1024). One block of 256 threads per row.
// ---------------------------------------------------------------------------
__global__ void ln_kernel(const float* __restrict__ X, const float* __restrict__ g,
                          const float* __restrict__ be, float* __restrict__ Y) {
    int row = blockIdx.x;
    int tid = threadIdx.x;
    const float* xr = X + (size_t)row * Cn;

    float v[4];
    float s = 0.f, ss = 0.f;
#pragma unroll
    for (int i = 0; i < 4; i++) {
        v[i] = xr[tid + i * 256];
        s += v[i];
        ss += v[i] * v[i];
    }

    __shared__ float rs[256], rss[256];
    rs[tid] = s;
    rss[tid] = ss;
    __syncthreads();
    for (int off = 128; off; off >>= 1) {
        if (tid < off) {
            rs[tid] += rs[tid + off];
            rss[tid] += rss[tid + off];
        }
        __syncthreads();
    }
    float mean = rs[0] * (1.f / Cn);
    float var = rss[0] * (1.f / Cn) - mean * mean;
    float rstd = rsqrtf(var + EPSn);

    float* yr = Y + (size_t)row * Cn;
#pragma unroll
    for (int i = 0; i < 4; i++) {
        int c = tid + i * 256;
        yr[c] = (v[i] - mean) * rstd * g[c] + be[c];
    }
}

// ---------------------------------------------------------------------------
// Launch
// ---------------------------------------------------------------------------
static float* symaddr(const void* sym) {
    void* p = nullptr;
    cudaGetSymbolAddress(&p, sym);
    return (float*)p;
}

extern "C" void kernel_launch(void* const* d_in, const int* in_sizes, int n_in,
                              void* d_out, int out_size) {
    const float* x   = (const float*)d_in[0];
    const float* Wq  = (const float*)d_in[1];
    const float* bq  = (const float*)d_in[2];
    const float* Wk  = (const float*)d_in[3];
    const float* bk  = (const float*)d_in[4];
    const float* Wv  = (const float*)d_in[5];
    const float* bv  = (const float*)d_in[6];
    const float* Wp  = (const float*)d_in[7];
    const float* bp  = (const float*)d_in[8];
    const float* W1  = (const float*)d_in[9];
    const float* b1  = (const float*)d_in[10];
    const float* W2  = (const float*)d_in[11];
    const float* b2  = (const float*)d_in[12];
    const float* g1  = (const float*)d_in[13];
    const float* be1 = (const float*)d_in[14];
    const float* g2  = (const float*)d_in[15];
    const float* be2 = (const float*)d_in[16];
    float* out = (float*)d_out;

    float* Wqt = symaddr(g_Wqt);
    float* Wkt = symaddr(g_Wkt);
    float* Wvt = symaddr(g_Wvt);
    float* qb  = symaddr(g_q);
    float* kb  = symaddr(g_k);
    float* vb  = symaddr(g_v);
    float* att = symaddr(g_att);
    float* t0  = symaddr(g_t0);
    float* hb  = symaddr(g_h);
    float* f1  = symaddr(g_f1);
    float* f2  = symaddr(g_f2);

    const int M = Bn * Tn;  // 4096

    // 1) weight transposes (H,C,HS) -> (C, H*HS)
    wtrans_kernel<<<(Hn * Cn * HSn) / 256, 256>>>(Wq, Wqt);
    wtrans_kernel<<<(Hn * Cn * HSn) / 256, 256>>>(Wk, Wkt);
    wtrans_kernel<<<(Hn * Cn * HSn) / 256, 256>>>(Wv, Wvt);

    // 2) QKV projections: [4096,1024] @ [1024,1024] + bias
    sgemm_kernel<false><<<dim3(Cn / 64, M / 64), 256>>>(x, Wqt, bq, qb, M, Cn, Cn);
    sgemm_kernel<false><<<dim3(Cn / 64, M / 64), 256>>>(x, Wkt, bk, kb, M, Cn, Cn);
    sgemm_kernel<false><<<dim3(Cn / 64, M / 64), 256>>>(x, Wvt, bv, vb, M, Cn, Cn);

    // 3) causal attention (concat-head output directly)
    attn_kernel<<<dim3(Tn / 4, Hn, Bn), 128>>>(qb, kb, vb, att);

    // 4) output projection
    sgemm_kernel<false><<<dim3(Cn / 64, M / 64), 256>>>(att, Wp, bp, t0, M, Cn, Cn);

    // 5) LN1
    ln_kernel<<<M, 256>>>(t0, g1, be1, hb);

    // 6) FFN
    sgemm_kernel<true><<<dim3(FFn / 64, M / 64), 256>>>(hb, W1, b1, f1, M, FFn, Cn);
    sgemm_kernel<true><<<dim3(Cn / 64, M / 64), 256>>>(f1, W2, b2, f2, M, Cn, FFn);

    // 7) LN2 -> output
    ln_kernel<<<M, 256>>>(f2, g2, be2, out);
}

// round 2
// speedup vs baseline: 2.5358x; 2.5358x over previous
#include <cuda_runtime.h>
#include <cuda_bf16.h>
#include <math.h>

// Problem constants
#define Bn 2
#define Tn 2048
#define Cn 1024
#define Hn 16
#define HSn 64
#define FFn 4096
#define EPSn 1e-5f
#define NEG_BIG (-1e30f)

// ---------------------------------------------------------------------------
// Device scratch
// ---------------------------------------------------------------------------
__device__ float g_Wqt[Cn * Cn];          // [C, H*HS]
__device__ float g_Wkt[Cn * Cn];
__device__ float g_Wvt[Cn * Cn];
__device__ float g_q[Bn * Tn * Cn];       // [B,T,H,HS]
__device__ float g_k[Bn * Tn * Cn];
__device__ float g_v[Bn * Tn * Cn];
__device__ float g_att[Bn * Tn * Cn];     // concat heads [B,T,C]
__device__ float g_t0[Bn * Tn * Cn];      // proj out (pre-LN)
__device__ float g_h[Bn * Tn * Cn];       // LN1 out
__device__ float g_f1[Bn * Tn * FFn];     // FFN mid
__device__ float g_f2[Bn * Tn * Cn];      // FFN out (pre-LN)

// ---------------------------------------------------------------------------
// Weight transpose: W[H,C,HS] -> Wt[C, H*HS]
// ---------------------------------------------------------------------------
__global__ void wtrans_kernel(const float* __restrict__ W, float* __restrict__ Wt) {
    int idx = blockIdx.x * 256 + threadIdx.x;
    int d = idx & (HSn - 1);
    int c = (idx / HSn) & (Cn - 1);
    int h = idx / (HSn * Cn);
    Wt[(size_t)c * Cn + h * HSn + d] = W[idx];
}

// ---------------------------------------------------------------------------
// SGEMM: C[M,N] = A[M,K] @ B[K,N] + bias, optional ReLU.
// 128x128 tile, Kstep 16, 256 threads, 8x8 per thread (4x4 quads).
// ---------------------------------------------------------------------------
template <bool RELU>
__global__ void __launch_bounds__(256, 2)
sgemm_kernel(const float* __restrict__ A, const float* __restrict__ B,
             const float* __restrict__ bias, float* __restrict__ Cout,
             int M, int N, int K) {
    __shared__ float As[16][132];   // [k][m] transposed, padded
    __shared__ float Bs[16][128];   // [k][n]

    int tid = threadIdx.x;
    int m0 = blockIdx.y * 128;
    int n0 = blockIdx.x * 128;
    int ty = tid >> 4;       // 0..15
    int tx = tid & 15;       // 0..15

    float acc[8][8];
#pragma unroll
    for (int i = 0; i < 8; i++)
#pragma unroll
        for (int j = 0; j < 8; j++) acc[i][j] = 0.f;

    const float* Ag = A + (size_t)m0 * K;
    const float* Bg = B + n0;

    for (int k0 = 0; k0 < K; k0 += 16) {
#pragma unroll
        for (int i = 0; i < 2; i++) {
            int idx = tid + i * 256;          // 0..511
            int m = idx >> 2;                 // 0..127
            int kq = idx & 3;                 // 0..3
            float4 a = *(const float4*)&Ag[(size_t)m * K + k0 + kq * 4];
            As[kq * 4 + 0][m] = a.x;
            As[kq * 4 + 1][m] = a.y;
            As[kq * 4 + 2][m] = a.z;
            As[kq * 4 + 3][m] = a.w;
        }
#pragma unroll
        for (int i = 0; i < 2; i++) {
            int idx = tid + i * 256;          // 0..511
            int kk = idx >> 5;                // 0..15
            int nq = idx & 31;                // 0..31
            *(float4*)&Bs[kk][nq * 4] =
                *(const float4*)&Bg[(size_t)(k0 + kk) * N + nq * 4];
        }
        __syncthreads();

#pragma unroll
        for (int kk = 0; kk < 16; kk++) {
            float4 a0 = *(const float4*)&As[kk][ty * 4];
            float4 a1 = *(const float4*)&As[kk][ty * 4 + 64];
            float4 b0 = *(const float4*)&Bs[kk][tx * 4];
            float4 b1 = *(const float4*)&Bs[kk][tx * 4 + 64];
            float av[8] = {a0.x, a0.y, a0.z, a0.w, a1.x, a1.y, a1.z, a1.w};
            float bv[8] = {b0.x, b0.y, b0.z, b0.w, b1.x, b1.y, b1.z, b1.w};
#pragma unroll
            for (int i = 0; i < 8; i++)
#pragma unroll
                for (int j = 0; j < 8; j++) acc[i][j] = fmaf(av[i], bv[j], acc[i][j]);
        }
        __syncthreads();
    }

    float4 bb0 = *(const float4*)&bias[n0 + tx * 4];
    float4 bb1 = *(const float4*)&bias[n0 + tx * 4 + 64];
    float bv[8] = {bb0.x, bb0.y, bb0.z, bb0.w, bb1.x, bb1.y, bb1.z, bb1.w};

#pragma unroll
    for (int i = 0; i < 8; i++) {
        int m = m0 + ty * 4 + (i & 3) + (i >> 2) * 64;
#pragma unroll
        for (int half = 0; half < 2; half++) {
            float4 r;
            r.x = acc[i][half * 4 + 0] + bv[half * 4 + 0];
            r.y = acc[i][half * 4 + 1] + bv[half * 4 + 1];
            r.z = acc[i][half * 4 + 2] + bv[half * 4 + 2];
            r.w = acc[i][half * 4 + 3] + bv[half * 4 + 3];
            if (RELU) {
                r.x = fmaxf(r.x, 0.f); r.y = fmaxf(r.y, 0.f);
                r.z = fmaxf(r.z, 0.f); r.w = fmaxf(r.w, 0.f);
            }
            *(float4*)&Cout[(size_t)m * N + n0 + tx * 4 + half * 64] = r;
        }
    }
}

// ---------------------------------------------------------------------------
// Tiled flash attention (fp32). Q/K/V layout [B,T,H,HS].
// 64-query x 32-key tiles. 256 threads = 16x16. Thread (ty,tx):
//   S phase: rows ty*4..+3, key-cols tx*2..+1
//   PV phase: rows ty*4..+3, d-cols tx*4..+3
// Row softmax stats reduced across tx via half-warp shuffles.
// ---------------------------------------------------------------------------
__global__ void __launch_bounds__(256) attn_kernel(
    const float* __restrict__ Q, const float* __restrict__ K,
    const float* __restrict__ V, float* __restrict__ O) {
    __shared__ float Qs[64][68];   // [d][row]
    __shared__ float Ks[64][34];   // [d][key]
    __shared__ float Vs[32][64];   // [key][d]
    __shared__ float Ps[32][68];   // [key][row]

    int tid = threadIdx.x;
    int ty = tid >> 4;
    int tx = tid & 15;
    int q0 = blockIdx.x * 64;
    int h = blockIdx.y;
    int b = blockIdx.z;

    const float* Qg = Q + ((size_t)(b * Tn + q0)) * Cn + h * HSn;
    const float* Kg = K + ((size_t)(b * Tn)) * Cn + h * HSn;
    const float* Vg = V + ((size_t)(b * Tn)) * Cn + h * HSn;

    // Load Q tile transposed: Qs[d][row]
#pragma unroll
    for (int i = 0; i < 4; i++) {
        int idx = tid + i * 256;          // 0..1023
        int row = idx >> 4;               // 0..63
        int dq = idx & 15;                // 0..15
        float4 qv = *(const float4*)&Qg[(size_t)row * Cn + dq * 4];
        Qs[dq * 4 + 0][row] = qv.x;
        Qs[dq * 4 + 1][row] = qv.y;
        Qs[dq * 4 + 2][row] = qv.z;
        Qs[dq * 4 + 3][row] = qv.w;
    }

    float mrow[4], lrow[4], o[4][4];
#pragma unroll
    for (int r = 0; r < 4; r++) {
        mrow[r] = NEG_BIG;
        lrow[r] = 0.f;
#pragma unroll
        for (int d = 0; d < 4; d++) o[r][d] = 0.f;
    }

    const float scale = 0.125f;   // HS^-0.5
    int nkeys = q0 + 64;

    for (int s0 = 0; s0 < nkeys; s0 += 32) {
        __syncthreads();   // previous PV done before overwriting Ks/Vs; also orders Q load
        // Load K tile transposed + V tile
#pragma unroll
        for (int i = 0; i < 2; i++) {
            int idx = tid + i * 256;      // 0..511
            int j = idx >> 4;             // 0..31
            int dq = idx & 15;            // 0..15
            float4 kv = *(const float4*)&Kg[(size_t)(s0 + j) * Cn + dq * 4];
            Ks[dq * 4 + 0][j] = kv.x;
            Ks[dq * 4 + 1][j] = kv.y;
            Ks[dq * 4 + 2][j] = kv.z;
            Ks[dq * 4 + 3][j] = kv.w;
            float4 vv = *(const float4*)&Vg[(size_t)(s0 + j) * Cn + dq * 4];
            *(float4*)&Vs[j][dq * 4] = vv;
        }
        __syncthreads();

        // S = Q @ K^T  (4 rows x 2 cols per thread)
        float s[4][2];
#pragma unroll
        for (int r = 0; r < 4; r++) { s[r][0] = 0.f; s[r][1] = 0.f; }
#pragma unroll
        for (int d = 0; d < 64; d++) {
            float4 qv = *(const float4*)&Qs[d][ty * 4];
            float2 kv = *(const float2*)&Ks[d][tx * 2];
            s[0][0] = fmaf(qv.x, kv.x, s[0][0]);
            s[0][1] = fmaf(qv.x, kv.y, s[0][1]);
            s[1][0] = fmaf(qv.y, kv.x, s[1][0]);
            s[1][1] = fmaf(qv.y, kv.y, s[1][1]);
            s[2][0] = fmaf(qv.z, kv.x, s[2][0]);
            s[2][1] = fmaf(qv.z, kv.y, s[2][1]);
            s[3][0] = fmaf(qv.w, kv.x, s[3][0]);
            s[3][1] = fmaf(qv.w, kv.y, s[3][1]);
        }

        bool need_mask = (s0 + 31 > q0);
#pragma unroll
        for (int r = 0; r < 4; r++) {
            int t_g = q0 + ty * 4 + r;
            float sc0 = s[r][0] * scale;
            float sc1 = s[r][1] * scale;
            if (need_mask) {
                if (s0 + tx * 2 + 0 > t_g) sc0 = NEG_BIG;
                if (s0 + tx * 2 + 1 > t_g) sc1 = NEG_BIG;
            }
            // row max across this thread's 2 cols + 16-lane subgroup
            float mc = fmaxf(sc0, sc1);
#pragma unroll
            for (int off = 8; off; off >>= 1)
                mc = fmaxf(mc, __shfl_xor_sync(0xffffffffu, mc, off));
            float mnew = fmaxf(mrow[r], mc);
            float alpha = __expf(mrow[r] - mnew);
            mrow[r] = mnew;
            float p0 = __expf(sc0 - mnew);
            float p1 = __expf(sc1 - mnew);
            float ps = p0 + p1;
#pragma unroll
            for (int off = 8; off; off >>= 1)
                ps += __shfl_xor_sync(0xffffffffu, ps, off);
            lrow[r] = lrow[r] * alpha + ps;
#pragma unroll
            for (int d = 0; d < 4; d++) o[r][d] *= alpha;
            Ps[tx * 2 + 0][ty * 4 + r] = p0;
            Ps[tx * 2 + 1][ty * 4 + r] = p1;
        }
        __syncthreads();

        // O += P @ V  (4 rows x 4 d per thread)
#pragma unroll
        for (int sk = 0; sk < 32; sk++) {
            float4 pv = *(const float4*)&Ps[sk][ty * 4];
            float4 vv = *(const float4*)&Vs[sk][tx * 4];
            float pr[4] = {pv.x, pv.y, pv.z, pv.w};
            float vd[4] = {vv.x, vv.y, vv.z, vv.w};
#pragma unroll
            for (int r = 0; r < 4; r++)
#pragma unroll
                for (int d = 0; d < 4; d++) o[r][d] = fmaf(pr[r], vd[d], o[r][d]);
        }
    }

    // Write output
#pragma unroll
    for (int r = 0; r < 4; r++) {
        float inv = 1.f / lrow[r];
        float4 res;
        res.x = o[r][0] * inv;
        res.y = o[r][1] * inv;
        res.z = o[r][2] * inv;
        res.w = o[r][3] * inv;
        int t = q0 + ty * 4 + r;
        *(float4*)&O[((size_t)(b * Tn + t)) * Cn + h * HSn + tx * 4] = res;
    }
}

// ---------------------------------------------------------------------------
// LayerNorm over last dim (C=1024). One block of 256 threads per row.
// ---------------------------------------------------------------------------
__global__ void ln_kernel(const float* __restrict__ X, const float* __restrict__ g,
                          const float* __restrict__ be, float* __restrict__ Y) {
    int row = blockIdx.x;
    int tid = threadIdx.x;
    const float* xr = X + (size_t)row * Cn;

    float v[4];
    float s = 0.f, ss = 0.f;
#pragma unroll
    for (int i = 0; i < 4; i++) {
        v[i] = xr[tid + i * 256];
        s += v[i];
        ss += v[i] * v[i];
    }

    __shared__ float rs[256], rss[256];
    rs[tid] = s;
    rss[tid] = ss;
    __syncthreads();
    for (int off = 128; off; off >>= 1) {
        if (tid < off) {
            rs[tid] += rs[tid + off];
            rss[tid] += rss[tid + off];
        }
        __syncthreads();
    }
    float mean = rs[0] * (1.f / Cn);
    float var = rss[0] * (1.f / Cn) - mean * mean;
    float rstd = rsqrtf(var + EPSn);

    float* yr = Y + (size_t)row * Cn;
#pragma unroll
    for (int i = 0; i < 4; i++) {
        int c = tid + i * 256;
        yr[c] = (v[i] - mean) * rstd * g[c] + be[c];
    }
}

// ---------------------------------------------------------------------------
// Launch
// ---------------------------------------------------------------------------
static float* symaddr(const void* sym) {
    void* p = nullptr;
    cudaGetSymbolAddress(&p, sym);
    return (float*)p;
}

extern "C" void kernel_launch(void* const* d_in, const int* in_sizes, int n_in,
                              void* d_out, int out_size) {
    const float* x   = (const float*)d_in[0];
    const float* Wq  = (const float*)d_in[1];
    const float* bq  = (const float*)d_in[2];
    const float* Wk  = (const float*)d_in[3];
    const float* bk  = (const float*)d_in[4];
    const float* Wv  = (const float*)d_in[5];
    const float* bv  = (const float*)d_in[6];
    const float* Wp  = (const float*)d_in[7];
    const float* bp  = (const float*)d_in[8];
    const float* W1  = (const float*)d_in[9];
    const float* b1  = (const float*)d_in[10];
    const float* W2  = (const float*)d_in[11];
    const float* b2  = (const float*)d_in[12];
    const float* g1  = (const float*)d_in[13];
    const float* be1 = (const float*)d_in[14];
    const float* g2  = (const float*)d_in[15];
    const float* be2 = (const float*)d_in[16];
    float* out = (float*)d_out;

    float* Wqt = symaddr(g_Wqt);
    float* Wkt = symaddr(g_Wkt);
    float* Wvt = symaddr(g_Wvt);
    float* qb  = symaddr(g_q);
    float* kb  = symaddr(g_k);
    float* vb  = symaddr(g_v);
    float* att = symaddr(g_att);
    float* t0  = symaddr(g_t0);
    float* hb  = symaddr(g_h);
    float* f1  = symaddr(g_f1);
    float* f2  = symaddr(g_f2);

    const int M = Bn * Tn;  // 4096

    // 1) weight transposes
    wtrans_kernel<<<(Hn * Cn * HSn) / 256, 256>>>(Wq, Wqt);
    wtrans_kernel<<<(Hn * Cn * HSn) / 256, 256>>>(Wk, Wkt);
    wtrans_kernel<<<(Hn * Cn * HSn) / 256, 256>>>(Wv, Wvt);

    // 2) QKV projections
    sgemm_kernel<false><<<dim3(Cn / 128, M / 128), 256>>>(x, Wqt, bq, qb, M, Cn, Cn);
    sgemm_kernel<false><<<dim3(Cn / 128, M / 128), 256>>>(x, Wkt, bk, kb, M, Cn, Cn);
    sgemm_kernel<false><<<dim3(Cn / 128, M / 128), 256>>>(x, Wvt, bv, vb, M, Cn, Cn);

    // 3) tiled causal flash attention
    attn_kernel<<<dim3(Tn / 64, Hn, Bn), 256>>>(qb, kb, vb, att);

    // 4) output projection
    sgemm_kernel<false><<<dim3(Cn / 128, M / 128), 256>>>(att, Wp, bp, t0, M, Cn, Cn);

    // 5) LN1
    ln_kernel<<<M, 256>>>(t0, g1, be1, hb);

    // 6) FFN
    sgemm_kernel<true><<<dim3(FFn / 128, M / 128), 256>>>(hb, W1, b1, f1, M, FFn, Cn);
    sgemm_kernel<true><<<dim3(Cn / 128, M / 128), 256>>>(f1, W2, b2, f2, M, Cn, FFn);

    // 7) LN2 -> output
    ln_kernel<<<M, 256>>>(f2, g2, be2, out);
}

// round 4
// speedup vs baseline: 4.3354x; 1.7097x over previous
#include <cuda_runtime.h>
#include <cuda_bf16.h>
#include <math.h>
#include <stdint.h>

// Problem constants
#define Bn 2
#define Tn 2048
#define Cn 1024
#define Hn 16
#define HSn 64
#define FFn 4096
#define EPSn 1e-5f
#define NEG_BIG (-1e30f)
#define Mrows (Bn * Tn)   // 4096

// ===========================================================================
// PTX helpers (generic sm_80+ instructions only — no tcgen05 on this target)
// ===========================================================================
__device__ __forceinline__ uint32_t smem_u32(const void* p) {
    uint32_t a;
    asm("{ .reg .u64 t; cvta.to.shared.u64 t, %1; cvt.u32.u64 %0, t; }" : "=r"(a) : "l"(p));
    return a;
}

#define CP_ASYNC16(dst, src) \
    asm volatile("cp.async.cg.shared.global [%0], [%1], 16;" :: "r"(dst), "l"(src))
#define CP_ASYNC_COMMIT() asm volatile("cp.async.commit_group;" ::: "memory")
#define CP_ASYNC_WAIT0() asm volatile("cp.async.wait_group 0;" ::: "memory")
#define CP_ASYNC_WAIT1() asm volatile("cp.async.wait_group 1;" ::: "memory")

__device__ __forceinline__ void ldsm4(uint32_t r[4], uint32_t addr) {
    asm volatile("ldmatrix.sync.aligned.m8n8.x4.shared.b16 {%0,%1,%2,%3}, [%4];"
                 : "=r"(r[0]), "=r"(r[1]), "=r"(r[2]), "=r"(r[3]) : "r"(addr));
}

__device__ __forceinline__ void mma16816(float c[4], const uint32_t a[4],
                                         uint32_t b0, uint32_t b1) {
    asm volatile(
        "mma.sync.aligned.m16n8k16.row.col.f32.bf16.bf16.f32 "
        "{%0,%1,%2,%3}, {%4,%5,%6,%7}, {%8,%9}, {%0,%1,%2,%3};"
        : "+f"(c[0]), "+f"(c[1]), "+f"(c[2]), "+f"(c[3])
        : "r"(a[0]), "r"(a[1]), "r"(a[2]), "r"(a[3]), "r"(b0), "r"(b1));
}

// SW64 swizzle for 64-byte rows (8 rows x 64B atom): conflict-free ldmatrix
__device__ __forceinline__ uint32_t sw64(uint32_t b) { return b ^ ((b >> 3) & 0x30u); }

// ===========================================================================
// Device scratch
// ===========================================================================
__device__ __align__(256) __nv_bfloat16 g_xh[Mrows * Cn], g_xl[Mrows * Cn];
__device__ __align__(256) __nv_bfloat16 g_Wqth[Cn * Cn], g_Wqtl[Cn * Cn];
__device__ __align__(256) __nv_bfloat16 g_Wkth[Cn * Cn], g_Wktl[Cn * Cn];
__device__ __align__(256) __nv_bfloat16 g_Wvth[Cn * Cn], g_Wvtl[Cn * Cn];
__device__ __align__(256) __nv_bfloat16 g_Wpth[Cn * Cn], g_Wptl[Cn * Cn];
__device__ __align__(256) __nv_bfloat16 g_W1th[FFn * Cn], g_W1tl[FFn * Cn];
__device__ __align__(256) __nv_bfloat16 g_W2th[Cn * FFn], g_W2tl[Cn * FFn];
__device__ __align__(256) __nv_bfloat16 g_atth[Mrows * Cn], g_attl[Mrows * Cn];
__device__ __align__(256) __nv_bfloat16 g_hh[Mrows * Cn], g_hl[Mrows * Cn];
__device__ __align__(256) __nv_bfloat16 g_f1h[Mrows * FFn], g_f1l[Mrows * FFn];
__device__ __align__(256) float g_q[Mrows * Cn];
__device__ __align__(256) float g_k[Mrows * Cn];
__device__ __align__(256) float g_v[Mrows * Cn];
__device__ __align__(256) float g_t0[Mrows * Cn];
__device__ __align__(256) float g_f2[Mrows * Cn];

// ===========================================================================
// Elementwise split: fp32 -> (hi, lo) bf16
// ===========================================================================
__global__ void split_kernel(const float* __restrict__ in, __nv_bfloat16* __restrict__ oh,
                             __nv_bfloat16* __restrict__ ol) {
    int i = blockIdx.x * 256 + threadIdx.x;
    float v = in[i];
    __nv_bfloat16 h = __float2bfloat16(v);
    oh[i] = h;
    ol[i] = __float2bfloat16(v - __bfloat162float(h));
}

// ===========================================================================
// Tiled transpose+split: in [R, Cc] fp32 per batch -> out [Cc, R] bf16 hi/lo
// ===========================================================================
__global__ void transpose_split(const float* __restrict__ in, __nv_bfloat16* __restrict__ oh,
                                __nv_bfloat16* __restrict__ ol, int R, int Cc) {
    __shared__ float tile[32][33];
    size_t boff = (size_t)blockIdx.z * R * Cc;
    const float* ip = in + boff;
    int i0 = blockIdx.y * 32, j0 = blockIdx.x * 32;
#pragma unroll
    for (int k = threadIdx.y; k < 32; k += 8)
        tile[k][threadIdx.x] = ip[(size_t)(i0 + k) * Cc + j0 + threadIdx.x];
    __syncthreads();
#pragma unroll
    for (int k = threadIdx.y; k < 32; k += 8) {
        float v = tile[threadIdx.x][k];
        __nv_bfloat16 h = __float2bfloat16(v);
        size_t o = boff + (size_t)(j0 + k) * R + i0 + threadIdx.x;
        oh[o] = h;
        ol[o] = __float2bfloat16(v - __bfloat162float(h));
    }
}

// ===========================================================================
// Tensor-core GEMM via mma.sync, bf16 hi/lo split operands (3-term fp32 emu).
// C[M,N] = (Ahi+Alo)[M,K] @ (Bhi+Blo)[N,K]^T + bias, fused ReLU / split-out.
// CTA: 128x128 tile, 256 threads = 8 warps (4 M x 2 N), warp tile 32x64.
// K-chunk 32, 3-stage cp.async pipeline. Smem stage: Ahi|Alo|Bhi|Blo 8KB each.
// ===========================================================================
#define STAGE_BYTES 32768
#define GEMM_SMEM (3 * STAGE_BYTES)

template <bool SPLIT, bool RELU>
__global__ void __launch_bounds__(256, 1)
gemm_mma(const __nv_bfloat16* __restrict__ Ahi, const __nv_bfloat16* __restrict__ Alo,
         const __nv_bfloat16* __restrict__ Bhi, const __nv_bfloat16* __restrict__ Blo,
         const float* __restrict__ bias,
         float* __restrict__ Cf, __nv_bfloat16* __restrict__ Chi, __nv_bfloat16* __restrict__ Clo,
         int M, int N, int K) {
    extern __shared__ char dsmem[];
    uint32_t sb = smem_u32(dsmem);

    int tid = threadIdx.x;
    int wid = tid >> 5;
    int lane = tid & 31;
    int n0 = blockIdx.x * 128;
    int m0 = blockIdx.y * 128;
    int wm = wid & 3;          // 0..3 : M subtile
    int wn = wid >> 2;         // 0..1 : N subtile

    const int NC = K >> 5;     // 32-wide K chunks

    // ---- stage loader: 4 tiles (Ahi,Alo,Bhi,Blo) 128x32 bf16, 16B cp.async ----
    auto load_chunk = [&](int c, int stage) {
        uint32_t base = sb + (uint32_t)stage * STAGE_BYTES;
        size_t kof = (size_t)c * 32;
#pragma unroll
        for (int i = 0; i < 8; i++) {
            int g = i * 256 + tid;           // 0..2047
            int tilei = g >> 9;              // 0..3
            int idx = g & 511;
            int row = idx >> 2;              // 0..127
            int ch = idx & 3;                // 0..3 (16B chunks in 64B row)
            const __nv_bfloat16* src;
            if (tilei == 0)      src = Ahi + (size_t)(m0 + row) * K + kof + ch * 8;
            else if (tilei == 1) src = Alo + (size_t)(m0 + row) * K + kof + ch * 8;
            else if (tilei == 2) src = Bhi + (size_t)(n0 + row) * K + kof + ch * 8;
            else                 src = Blo + (size_t)(n0 + row) * K + kof + ch * 8;
            uint32_t dst = base + (uint32_t)tilei * 8192u + sw64((uint32_t)(row * 64 + ch * 16));
            CP_ASYNC16(dst, src);
        }
        CP_ASYNC_COMMIT();
    };

    float c[2][8][4];
#pragma unroll
    for (int mt = 0; mt < 2; mt++)
#pragma unroll
        for (int nt = 0; nt < 8; nt++)
#pragma unroll
            for (int j = 0; j < 4; j++) c[mt][nt][j] = 0.f;

    load_chunk(0, 0);
    load_chunk(1, 1);

    // fragment-load address components (lane-fixed)
    int arow = lane & 15;
    int aoff = (lane >> 4) * 16;
    int brow = ((lane >> 4) << 3) + (lane & 7);
    int boff = ((lane >> 3) & 1) * 16;

    for (int cc = 0; cc < NC; cc++) {
        if (cc == NC - 1) { CP_ASYNC_WAIT0(); } else { CP_ASYNC_WAIT1(); }
        __syncthreads();
        if (cc + 2 < NC) load_chunk(cc + 2, (cc + 2) % 3);

        uint32_t base = sb + (uint32_t)(cc % 3) * STAGE_BYTES;
#pragma unroll
        for (int k16 = 0; k16 < 2; k16++) {
            uint32_t ahi[2][4], alo[2][4];
#pragma unroll
            for (int mt = 0; mt < 2; mt++) {
                uint32_t byte = (uint32_t)((wm * 32 + mt * 16 + arow) * 64 + k16 * 32 + aoff);
                uint32_t sw = sw64(byte);
                ldsm4(ahi[mt], base + sw);
                ldsm4(alo[mt], base + 8192u + sw);
            }
            uint32_t bhi[4][4], blo[4][4];
#pragma unroll
            for (int nt16 = 0; nt16 < 4; nt16++) {
                uint32_t byte = (uint32_t)((wn * 64 + nt16 * 16 + brow) * 64 + k16 * 32 + boff);
                uint32_t sw = sw64(byte);
                ldsm4(bhi[nt16], base + 16384u + sw);
                ldsm4(blo[nt16], base + 24576u + sw);
            }
#pragma unroll
            for (int mt = 0; mt < 2; mt++)
#pragma unroll
                for (int nt = 0; nt < 8; nt++) {
                    uint32_t b0h = bhi[nt >> 1][(nt & 1) * 2];
                    uint32_t b1h = bhi[nt >> 1][(nt & 1) * 2 + 1];
                    uint32_t b0l = blo[nt >> 1][(nt & 1) * 2];
                    uint32_t b1l = blo[nt >> 1][(nt & 1) * 2 + 1];
                    mma16816(c[mt][nt], ahi[mt], b0h, b1h);
                    mma16816(c[mt][nt], ahi[mt], b0l, b1l);
                    mma16816(c[mt][nt], alo[mt], b0h, b1h);
                }
        }
    }

    // ---- epilogue ----
    int mbase = m0 + wm * 32;
    int nbase = n0 + wn * 64;
#pragma unroll
    for (int mt = 0; mt < 2; mt++) {
#pragma unroll
        for (int nt = 0; nt < 8; nt++) {
            int row0 = mbase + mt * 16 + (lane >> 2);
            int col = nbase + nt * 8 + (lane & 3) * 2;
            float b0 = bias[col], b1 = bias[col + 1];
#pragma unroll
            for (int half = 0; half < 2; half++) {
                int row = row0 + half * 8;
                float v0 = c[mt][nt][half * 2 + 0] + b0;
                float v1 = c[mt][nt][half * 2 + 1] + b1;
                if (RELU) { v0 = fmaxf(v0, 0.f); v1 = fmaxf(v1, 0.f); }
                if (SPLIT) {
                    __nv_bfloat16 h0 = __float2bfloat16(v0);
                    __nv_bfloat16 h1 = __float2bfloat16(v1);
                    __nv_bfloat162 hp; hp.x = h0; hp.y = h1;
                    __nv_bfloat162 lp;
                    lp.x = __float2bfloat16(v0 - __bfloat162float(h0));
                    lp.y = __float2bfloat16(v1 - __bfloat162float(h1));
                    *(__nv_bfloat162*)&Chi[(size_t)row * N + col] = hp;
                    *(__nv_bfloat162*)&Clo[(size_t)row * N + col] = lp;
                } else {
                    float2 r; r.x = v0; r.y = v1;
                    *(float2*)&Cf[(size_t)row * N + col] = r;
                }
            }
        }
    }
}

// ===========================================================================
// Tiled flash attention (fp32), epilogue writes bf16 hi/lo split.
// ===========================================================================
__global__ void __launch_bounds__(256) attn_kernel(
    const float* __restrict__ Q, const float* __restrict__ K,
    const float* __restrict__ V, __nv_bfloat16* __restrict__ Oh,
    __nv_bfloat16* __restrict__ Ol) {
    __shared__ float Qs[64][68];
    __shared__ float Ks[64][34];
    __shared__ float Vs[32][64];
    __shared__ float Ps[32][68];

    int tid = threadIdx.x;
    int ty = tid >> 4;
    int tx = tid & 15;
    int q0 = blockIdx.x * 64;
    int h = blockIdx.y;
    int b = blockIdx.z;

    const float* Qg = Q + ((size_t)(b * Tn + q0)) * Cn + h * HSn;
    const float* Kg = K + ((size_t)(b * Tn)) * Cn + h * HSn;
    const float* Vg = V + ((size_t)(b * Tn)) * Cn + h * HSn;

#pragma unroll
    for (int i = 0; i < 4; i++) {
        int idx = tid + i * 256;
        int row = idx >> 4;
        int dq = idx & 15;
        float4 qv = *(const float4*)&Qg[(size_t)row * Cn + dq * 4];
        Qs[dq * 4 + 0][row] = qv.x;
        Qs[dq * 4 + 1][row] = qv.y;
        Qs[dq * 4 + 2][row] = qv.z;
        Qs[dq * 4 + 3][row] = qv.w;
    }

    float mrow[4], lrow[4], o[4][4];
#pragma unroll
    for (int r = 0; r < 4; r++) {
        mrow[r] = NEG_BIG;
        lrow[r] = 0.f;
#pragma unroll
        for (int d = 0; d < 4; d++) o[r][d] = 0.f;
    }

    const float scale = 0.125f;
    int nkeys = q0 + 64;

    for (int s0 = 0; s0 < nkeys; s0 += 32) {
        __syncthreads();
#pragma unroll
        for (int i = 0; i < 2; i++) {
            int idx = tid + i * 256;
            int j = idx >> 4;
            int dq = idx & 15;
            float4 kv = *(const float4*)&Kg[(size_t)(s0 + j) * Cn + dq * 4];
            Ks[dq * 4 + 0][j] = kv.x;
            Ks[dq * 4 + 1][j] = kv.y;
            Ks[dq * 4 + 2][j] = kv.z;
            Ks[dq * 4 + 3][j] = kv.w;
            float4 vv = *(const float4*)&Vg[(size_t)(s0 + j) * Cn + dq * 4];
            *(float4*)&Vs[j][dq * 4] = vv;
        }
        __syncthreads();

        float s[4][2];
#pragma unroll
        for (int r = 0; r < 4; r++) { s[r][0] = 0.f; s[r][1] = 0.f; }
#pragma unroll
        for (int d = 0; d < 64; d++) {
            float4 qv = *(const float4*)&Qs[d][ty * 4];
            float2 kv = *(const float2*)&Ks[d][tx * 2];
            s[0][0] = fmaf(qv.x, kv.x, s[0][0]);
            s[0][1] = fmaf(qv.x, kv.y, s[0][1]);
            s[1][0] = fmaf(qv.y, kv.x, s[1][0]);
            s[1][1] = fmaf(qv.y, kv.y, s[1][1]);
            s[2][0] = fmaf(qv.z, kv.x, s[2][0]);
            s[2][1] = fmaf(qv.z, kv.y, s[2][1]);
            s[3][0] = fmaf(qv.w, kv.x, s[3][0]);
            s[3][1] = fmaf(qv.w, kv.y, s[3][1]);
        }

        bool need_mask = (s0 + 31 > q0);
#pragma unroll
        for (int r = 0; r < 4; r++) {
            int t_g = q0 + ty * 4 + r;
            float sc0 = s[r][0] * scale;
            float sc1 = s[r][1] * scale;
            if (need_mask) {
                if (s0 + tx * 2 + 0 > t_g) sc0 = NEG_BIG;
                if (s0 + tx * 2 + 1 > t_g) sc1 = NEG_BIG;
            }
            float mc = fmaxf(sc0, sc1);
#pragma unroll
            for (int off = 8; off; off >>= 1)
                mc = fmaxf(mc, __shfl_xor_sync(0xffffffffu, mc, off));
            float mnew = fmaxf(mrow[r], mc);
            float alpha = __expf(mrow[r] - mnew);
            mrow[r] = mnew;
            float p0 = __expf(sc0 - mnew);
            float p1 = __expf(sc1 - mnew);
            float ps = p0 + p1;
#pragma unroll
            for (int off = 8; off; off >>= 1)
                ps += __shfl_xor_sync(0xffffffffu, ps, off);
            lrow[r] = lrow[r] * alpha + ps;
#pragma unroll
            for (int d = 0; d < 4; d++) o[r][d] *= alpha;
            Ps[tx * 2 + 0][ty * 4 + r] = p0;
            Ps[tx * 2 + 1][ty * 4 + r] = p1;
        }
        __syncthreads();

#pragma unroll
        for (int sk = 0; sk < 32; sk++) {
            float4 pv = *(const float4*)&Ps[sk][ty * 4];
            float4 vv = *(const float4*)&Vs[sk][tx * 4];
            float pr[4] = {pv.x, pv.y, pv.z, pv.w};
            float vd[4] = {vv.x, vv.y, vv.z, vv.w};
#pragma unroll
            for (int r = 0; r < 4; r++)
#pragma unroll
                for (int d = 0; d < 4; d++) o[r][d] = fmaf(pr[r], vd[d], o[r][d]);
        }
    }

#pragma unroll
    for (int r = 0; r < 4; r++) {
        float inv = 1.f / lrow[r];
        int t = q0 + ty * 4 + r;
        size_t base = ((size_t)(b * Tn + t)) * Cn + h * HSn + tx * 4;
        __nv_bfloat162 hp[2], lp[2];
#pragma unroll
        for (int d = 0; d < 4; d += 2) {
            float v0 = o[r][d] * inv;
            float v1 = o[r][d + 1] * inv;
            __nv_bfloat16 h0 = __float2bfloat16(v0);
            __nv_bfloat16 h1 = __float2bfloat16(v1);
            hp[d / 2].x = h0; hp[d / 2].y = h1;
            lp[d / 2].x = __float2bfloat16(v0 - __bfloat162float(h0));
            lp[d / 2].y = __float2bfloat16(v1 - __bfloat162float(h1));
        }
        *(__nv_bfloat162*)&Oh[base] = hp[0];
        *(__nv_bfloat162*)&Oh[base + 2] = hp[1];
        *(__nv_bfloat162*)&Ol[base] = lp[0];
        *(__nv_bfloat162*)&Ol[base + 2] = lp[1];
    }
}

// ===========================================================================
// LayerNorm: fp32 out, or bf16 hi/lo split out
// ===========================================================================
template <bool SPLIT>
__global__ void ln_kernel(const float* __restrict__ X, const float* __restrict__ g,
                          const float* __restrict__ be, float* __restrict__ Y,
                          __nv_bfloat16* __restrict__ Yh, __nv_bfloat16* __restrict__ Yl) {
    int row = blockIdx.x;
    int tid = threadIdx.x;
    const float* xr = X + (size_t)row * Cn;

    float v[4];
    float s = 0.f, ss = 0.f;
#pragma unroll
    for (int i = 0; i < 4; i++) {
        v[i] = xr[tid + i * 256];
        s += v[i];
        ss += v[i] * v[i];
    }

    __shared__ float rs[256], rss[256];
    rs[tid] = s;
    rss[tid] = ss;
    __syncthreads();
    for (int off = 128; off; off >>= 1) {
        if (tid < off) {
            rs[tid] += rs[tid + off];
            rss[tid] += rss[tid + off];
        }
        __syncthreads();
    }
    float mean = rs[0] * (1.f / Cn);
    float var = rss[0] * (1.f / Cn) - mean * mean;
    float rstd = rsqrtf(var + EPSn);

#pragma unroll
    for (int i = 0; i < 4; i++) {
        int ccol = tid + i * 256;
        float y = (v[i] - mean) * rstd * g[ccol] + be[ccol];
        if (SPLIT) {
            __nv_bfloat16 h = __float2bfloat16(y);
            Yh[(size_t)row * Cn + ccol] = h;
            Yl[(size_t)row * Cn + ccol] = __float2bfloat16(y - __bfloat162float(h));
        } else {
            Y[(size_t)row * Cn + ccol] = y;
        }
    }
}

// ===========================================================================
// Launch
// ===========================================================================
static float* symaddrf(const void* sym) {
    void* p = nullptr;
    cudaGetSymbolAddress(&p, sym);
    return (float*)p;
}
static __nv_bfloat16* symaddrb(const void* sym) {
    void* p = nullptr;
    cudaGetSymbolAddress(&p, sym);
    return (__nv_bfloat16*)p;
}

extern "C" void kernel_launch(void* const* d_in, const int* in_sizes, int n_in,
                              void* d_out, int out_size) {
    const float* x   = (const float*)d_in[0];
    const float* Wq  = (const float*)d_in[1];
    const float* bq  = (const float*)d_in[2];
    const float* Wk  = (const float*)d_in[3];
    const float* bk  = (const float*)d_in[4];
    const float* Wv  = (const float*)d_in[5];
    const float* bv  = (const float*)d_in[6];
    const float* Wp  = (const float*)d_in[7];
    const float* bp  = (const float*)d_in[8];
    const float* W1  = (const float*)d_in[9];
    const float* b1  = (const float*)d_in[10];
    const float* W2  = (const float*)d_in[11];
    const float* b2  = (const float*)d_in[12];
    const float* g1  = (const float*)d_in[13];
    const float* be1 = (const float*)d_in[14];
    const float* g2  = (const float*)d_in[15];
    const float* be2 = (const float*)d_in[16];
    float* out = (float*)d_out;

    __nv_bfloat16 *xh = symaddrb(g_xh), *xl = symaddrb(g_xl);
    __nv_bfloat16 *Wqth = symaddrb(g_Wqth), *Wqtl = symaddrb(g_Wqtl);
    __nv_bfloat16 *Wkth = symaddrb(g_Wkth), *Wktl = symaddrb(g_Wktl);
    __nv_bfloat16 *Wvth = symaddrb(g_Wvth), *Wvtl = symaddrb(g_Wvtl);
    __nv_bfloat16 *Wpth = symaddrb(g_Wpth), *Wptl = symaddrb(g_Wptl);
    __nv_bfloat16 *W1th = symaddrb(g_W1th), *W1tl = symaddrb(g_W1tl);
    __nv_bfloat16 *W2th = symaddrb(g_W2th), *W2tl = symaddrb(g_W2tl);
    __nv_bfloat16 *atth = symaddrb(g_atth), *attl = symaddrb(g_attl);
    __nv_bfloat16 *hh = symaddrb(g_hh), *hl = symaddrb(g_hl);
    __nv_bfloat16 *f1h = symaddrb(g_f1h), *f1l = symaddrb(g_f1l);
    float *qb = symaddrf(g_q), *kb = symaddrf(g_k), *vb = symaddrf(g_v);
    float *t0 = symaddrf(g_t0), *f2 = symaddrf(g_f2);

    cudaFuncSetAttribute(gemm_mma<false, false>, cudaFuncAttributeMaxDynamicSharedMemorySize, GEMM_SMEM);
    cudaFuncSetAttribute(gemm_mma<true, true>,   cudaFuncAttributeMaxDynamicSharedMemorySize, GEMM_SMEM);
    cudaFuncSetAttribute(gemm_mma<false, true>,  cudaFuncAttributeMaxDynamicSharedMemorySize, GEMM_SMEM);

    const int M = Mrows;
    dim3 tb(32, 8);

    // 1) split x, transpose+split weights
    split_kernel<<<(M * Cn) / 256, 256>>>(x, xh, xl);
    transpose_split<<<dim3(HSn / 32, Cn / 32, Hn), tb>>>(Wq, Wqth, Wqtl, Cn, HSn);
    transpose_split<<<dim3(HSn / 32, Cn / 32, Hn), tb>>>(Wk, Wkth, Wktl, Cn, HSn);
    transpose_split<<<dim3(HSn / 32, Cn / 32, Hn), tb>>>(Wv, Wvth, Wvtl, Cn, HSn);
    transpose_split<<<dim3(Cn / 32, Cn / 32, 1), tb>>>(Wp, Wpth, Wptl, Cn, Cn);
    transpose_split<<<dim3(FFn / 32, Cn / 32, 1), tb>>>(W1, W1th, W1tl, Cn, FFn);
    transpose_split<<<dim3(Cn / 32, FFn / 32, 1), tb>>>(W2, W2th, W2tl, FFn, Cn);

    // 2) QKV projections (tensor core mma.sync)
    gemm_mma<false, false><<<dim3(Cn / 128, M / 128), 256, GEMM_SMEM>>>(
        xh, xl, Wqth, Wqtl, bq, qb, nullptr, nullptr, M, Cn, Cn);
    gemm_mma<false, false><<<dim3(Cn / 128, M / 128), 256, GEMM_SMEM>>>(
        xh, xl, Wkth, Wktl, bk, kb, nullptr, nullptr, M, Cn, Cn);
    gemm_mma<false, false><<<dim3(Cn / 128, M / 128), 256, GEMM_SMEM>>>(
        xh, xl, Wvth, Wvtl, bv, vb, nullptr, nullptr, M, Cn, Cn);

    // 3) flash attention (writes split bf16)
    attn_kernel<<<dim3(Tn / 64, Hn, Bn), 256>>>(qb, kb, vb, atth, attl);

    // 4) output projection
    gemm_mma<false, false><<<dim3(Cn / 128, M / 128), 256, GEMM_SMEM>>>(
        atth, attl, Wpth, Wptl, bp, t0, nullptr, nullptr, M, Cn, Cn);

    // 5) LN1 -> split
    ln_kernel<true><<<M, 256>>>(t0, g1, be1, nullptr, hh, hl);

    // 6) FFN
    gemm_mma<true, true><<<dim3(FFn / 128, M / 128), 256, GEMM_SMEM>>>(
        hh, hl, W1th, W1tl, b1, nullptr, f1h, f1l, M, FFn, Cn);
    gemm_mma<false, true><<<dim3(Cn / 128, M / 128), 256, GEMM_SMEM>>>(
        f1h, f1l, W2th, W2tl, b2, f2, nullptr, nullptr, M, Cn, FFn);

    // 7) LN2 -> output
    ln_kernel<false><<<M, 256>>>(f2, g2, be2, out, nullptr, nullptr);
}

// round 5
// speedup vs baseline: 6.2427x; 1.4399x over previous
#include <cuda_runtime.h>
#include <cuda_bf16.h>
#include <math.h>
#include <stdint.h>

// Problem constants
#define Bn 2
#define Tn 2048
#define Cn 1024
#define Hn 16
#define HSn 64
#define FFn 4096
#define EPSn 1e-5f
#define NEG_BIG (-1e30f)
#define Mrows (Bn * Tn)   // 4096

// ===========================================================================
// PTX helpers (generic sm_80+ only)
// ===========================================================================
__device__ __forceinline__ uint32_t smem_u32(const void* p) {
    uint32_t a;
    asm("{ .reg .u64 t; cvta.to.shared.u64 t, %1; cvt.u32.u64 %0, t; }" : "=r"(a) : "l"(p));
    return a;
}

#define CP_ASYNC16(dst, src) \
    asm volatile("cp.async.cg.shared.global [%0], [%1], 16;" :: "r"(dst), "l"(src))
#define CP_ASYNC_COMMIT() asm volatile("cp.async.commit_group;" ::: "memory")
#define CP_ASYNC_WAIT0() asm volatile("cp.async.wait_group 0;" ::: "memory")
#define CP_ASYNC_WAIT1() asm volatile("cp.async.wait_group 1;" ::: "memory")

__device__ __forceinline__ void ldsm4(uint32_t r[4], uint32_t addr) {
    asm volatile("ldmatrix.sync.aligned.m8n8.x4.shared.b16 {%0,%1,%2,%3}, [%4];"
                 : "=r"(r[0]), "=r"(r[1]), "=r"(r[2]), "=r"(r[3]) : "r"(addr));
}
__device__ __forceinline__ void ldsm4t(uint32_t r[4], uint32_t addr) {
    asm volatile("ldmatrix.sync.aligned.m8n8.x4.trans.shared.b16 {%0,%1,%2,%3}, [%4];"
                 : "=r"(r[0]), "=r"(r[1]), "=r"(r[2]), "=r"(r[3]) : "r"(addr));
}

__device__ __forceinline__ void mma16816(float c[4], const uint32_t a[4],
                                         uint32_t b0, uint32_t b1) {
    asm volatile(
        "mma.sync.aligned.m16n8k16.row.col.f32.bf16.bf16.f32 "
        "{%0,%1,%2,%3}, {%4,%5,%6,%7}, {%8,%9}, {%0,%1,%2,%3};"
        : "+f"(c[0]), "+f"(c[1]), "+f"(c[2]), "+f"(c[3])
        : "r"(a[0]), "r"(a[1]), "r"(a[2]), "r"(a[3]), "r"(b0), "r"(b1));
}

__device__ __forceinline__ uint32_t sw64(uint32_t b) { return b ^ ((b >> 3) & 0x30u); }
__device__ __forceinline__ uint32_t sw128(uint32_t b) { return b ^ ((b >> 3) & 0x70u); }

// ===========================================================================
// Device scratch
// ===========================================================================
__device__ __align__(256) __nv_bfloat16 g_xh[Mrows * Cn], g_xl[Mrows * Cn];
__device__ __align__(256) __nv_bfloat16 g_Wqth[Cn * Cn], g_Wqtl[Cn * Cn];
__device__ __align__(256) __nv_bfloat16 g_Wkth[Cn * Cn], g_Wktl[Cn * Cn];
__device__ __align__(256) __nv_bfloat16 g_Wvth[Cn * Cn], g_Wvtl[Cn * Cn];
__device__ __align__(256) __nv_bfloat16 g_Wpth[Cn * Cn], g_Wptl[Cn * Cn];
__device__ __align__(256) __nv_bfloat16 g_W1th[FFn * Cn], g_W1tl[FFn * Cn];
__device__ __align__(256) __nv_bfloat16 g_W2th[Cn * FFn], g_W2tl[Cn * FFn];
__device__ __align__(256) __nv_bfloat16 g_qh[Mrows * Cn], g_ql[Mrows * Cn];
__device__ __align__(256) __nv_bfloat16 g_kh[Mrows * Cn], g_kl[Mrows * Cn];
__device__ __align__(256) __nv_bfloat16 g_vh[Mrows * Cn], g_vl[Mrows * Cn];
__device__ __align__(256) __nv_bfloat16 g_atth[Mrows * Cn], g_attl[Mrows * Cn];
__device__ __align__(256) __nv_bfloat16 g_hh[Mrows * Cn], g_hl[Mrows * Cn];
__device__ __align__(256) __nv_bfloat16 g_f1h[Mrows * FFn], g_f1l[Mrows * FFn];
__device__ __align__(256) float g_t0[Mrows * Cn];
__device__ __align__(256) float g_f2[Mrows * Cn];

// ===========================================================================
// Elementwise split: fp32 -> (hi, lo) bf16
// ===========================================================================
__global__ void split_kernel(const float* __restrict__ in, __nv_bfloat16* __restrict__ oh,
                             __nv_bfloat16* __restrict__ ol) {
    int i = blockIdx.x * 256 + threadIdx.x;
    float v = in[i];
    __nv_bfloat16 h = __float2bfloat16(v);
    oh[i] = h;
    ol[i] = __float2bfloat16(v - __bfloat162float(h));
}

// ===========================================================================
// Tiled transpose+split
// ===========================================================================
__global__ void transpose_split(const float* __restrict__ in, __nv_bfloat16* __restrict__ oh,
                                __nv_bfloat16* __restrict__ ol, int R, int Cc) {
    __shared__ float tile[32][33];
    size_t boff = (size_t)blockIdx.z * R * Cc;
    const float* ip = in + boff;
    int i0 = blockIdx.y * 32, j0 = blockIdx.x * 32;
#pragma unroll
    for (int k = threadIdx.y; k < 32; k += 8)
        tile[k][threadIdx.x] = ip[(size_t)(i0 + k) * Cc + j0 + threadIdx.x];
    __syncthreads();
#pragma unroll
    for (int k = threadIdx.y; k < 32; k += 8) {
        float v = tile[threadIdx.x][k];
        __nv_bfloat16 h = __float2bfloat16(v);
        size_t o = boff + (size_t)(j0 + k) * R + i0 + threadIdx.x;
        oh[o] = h;
        ol[o] = __float2bfloat16(v - __bfloat162float(h));
    }
}

// ===========================================================================
// Tensor-core GEMM via mma.sync, bf16 hi/lo split operands (3-term fp32 emu).
// ===========================================================================
#define STAGE_BYTES 32768
#define GEMM_SMEM (3 * STAGE_BYTES)

template <bool SPLIT, bool RELU>
__global__ void __launch_bounds__(256, 1)
gemm_mma(const __nv_bfloat16* __restrict__ Ahi, const __nv_bfloat16* __restrict__ Alo,
         const __nv_bfloat16* __restrict__ Bhi, const __nv_bfloat16* __restrict__ Blo,
         const float* __restrict__ bias,
         float* __restrict__ Cf, __nv_bfloat16* __restrict__ Chi, __nv_bfloat16* __restrict__ Clo,
         int M, int N, int K) {
    extern __shared__ char dsmem[];
    uint32_t sb = smem_u32(dsmem);

    int tid = threadIdx.x;
    int wid = tid >> 5;
    int lane = tid & 31;
    int n0 = blockIdx.x * 128;
    int m0 = blockIdx.y * 128;
    int wm = wid & 3;
    int wn = wid >> 2;

    const int NC = K >> 5;

    auto load_chunk = [&](int c, int stage) {
        uint32_t base = sb + (uint32_t)stage * STAGE_BYTES;
        size_t kof = (size_t)c * 32;
#pragma unroll
        for (int i = 0; i < 8; i++) {
            int g = i * 256 + tid;
            int tilei = g >> 9;
            int idx = g & 511;
            int row = idx >> 2;
            int ch = idx & 3;
            const __nv_bfloat16* src;
            if (tilei == 0)      src = Ahi + (size_t)(m0 + row) * K + kof + ch * 8;
            else if (tilei == 1) src = Alo + (size_t)(m0 + row) * K + kof + ch * 8;
            else if (tilei == 2) src = Bhi + (size_t)(n0 + row) * K + kof + ch * 8;
            else                 src = Blo + (size_t)(n0 + row) * K + kof + ch * 8;
            uint32_t dst = base + (uint32_t)tilei * 8192u + sw64((uint32_t)(row * 64 + ch * 16));
            CP_ASYNC16(dst, src);
        }
        CP_ASYNC_COMMIT();
    };

    float c[2][8][4];
#pragma unroll
    for (int mt = 0; mt < 2; mt++)
#pragma unroll
        for (int nt = 0; nt < 8; nt++)
#pragma unroll
            for (int j = 0; j < 4; j++) c[mt][nt][j] = 0.f;

    load_chunk(0, 0);
    load_chunk(1, 1);

    int arow = lane & 15;
    int aoff = (lane >> 4) * 16;
    int brow = ((lane >> 4) << 3) + (lane & 7);
    int boff = ((lane >> 3) & 1) * 16;

    for (int cc = 0; cc < NC; cc++) {
        if (cc == NC - 1) { CP_ASYNC_WAIT0(); } else { CP_ASYNC_WAIT1(); }
        __syncthreads();
        if (cc + 2 < NC) load_chunk(cc + 2, (cc + 2) % 3);

        uint32_t base = sb + (uint32_t)(cc % 3) * STAGE_BYTES;
#pragma unroll
        for (int k16 = 0; k16 < 2; k16++) {
            uint32_t ahi[2][4], alo[2][4];
#pragma unroll
            for (int mt = 0; mt < 2; mt++) {
                uint32_t byte = (uint32_t)((wm * 32 + mt * 16 + arow) * 64 + k16 * 32 + aoff);
                uint32_t sw = sw64(byte);
                ldsm4(ahi[mt], base + sw);
                ldsm4(alo[mt], base + 8192u + sw);
            }
            uint32_t bhi[4][4], blo[4][4];
#pragma unroll
            for (int nt16 = 0; nt16 < 4; nt16++) {
                uint32_t byte = (uint32_t)((wn * 64 + nt16 * 16 + brow) * 64 + k16 * 32 + boff);
                uint32_t sw = sw64(byte);
                ldsm4(bhi[nt16], base + 16384u + sw);
                ldsm4(blo[nt16], base + 24576u + sw);
            }
#pragma unroll
            for (int mt = 0; mt < 2; mt++)
#pragma unroll
                for (int nt = 0; nt < 8; nt++) {
                    uint32_t b0h = bhi[nt >> 1][(nt & 1) * 2];
                    uint32_t b1h = bhi[nt >> 1][(nt & 1) * 2 + 1];
                    uint32_t b0l = blo[nt >> 1][(nt & 1) * 2];
                    uint32_t b1l = blo[nt >> 1][(nt & 1) * 2 + 1];
                    mma16816(c[mt][nt], ahi[mt], b0h, b1h);
                    mma16816(c[mt][nt], ahi[mt], b0l, b1l);
                    mma16816(c[mt][nt], alo[mt], b0h, b1h);
                }
        }
    }

    int mbase = m0 + wm * 32;
    int nbase = n0 + wn * 64;
#pragma unroll
    for (int mt = 0; mt < 2; mt++) {
#pragma unroll
        for (int nt = 0; nt < 8; nt++) {
            int row0 = mbase + mt * 16 + (lane >> 2);
            int col = nbase + nt * 8 + (lane & 3) * 2;
            float b0 = bias[col], b1 = bias[col + 1];
#pragma unroll
            for (int half = 0; half < 2; half++) {
                int row = row0 + half * 8;
                float v0 = c[mt][nt][half * 2 + 0] + b0;
                float v1 = c[mt][nt][half * 2 + 1] + b1;
                if (RELU) { v0 = fmaxf(v0, 0.f); v1 = fmaxf(v1, 0.f); }
                if (SPLIT) {
                    __nv_bfloat16 h0 = __float2bfloat16(v0);
                    __nv_bfloat16 h1 = __float2bfloat16(v1);
                    __nv_bfloat162 hp; hp.x = h0; hp.y = h1;
                    __nv_bfloat162 lp;
                    lp.x = __float2bfloat16(v0 - __bfloat162float(h0));
                    lp.y = __float2bfloat16(v1 - __bfloat162float(h1));
                    *(__nv_bfloat162*)&Chi[(size_t)row * N + col] = hp;
                    *(__nv_bfloat162*)&Clo[(size_t)row * N + col] = lp;
                } else {
                    float2 r; r.x = v0; r.y = v1;
                    *(float2*)&Cf[(size_t)row * N + col] = r;
                }
            }
        }
    }
}

// ===========================================================================
// Tensor-core flash attention with bf16 split emulation.
// CTA: 128 q rows, 8 warps x 16 rows. Key tiles of 64. Q/K/V split hi/lo.
// S = QK^T 3-term; online softmax on fp32 frags; P->A frag register remap;
// PV 3-term with V fragments via ldmatrix.trans.
// SMEM: Q 32KB (hi+lo) | K 16KB | V 16KB = 64KB.
// ===========================================================================
#define ATT_SMEM 65536

__global__ void __launch_bounds__(256, 2) attn_mma(
    const __nv_bfloat16* __restrict__ Qh, const __nv_bfloat16* __restrict__ Ql,
    const __nv_bfloat16* __restrict__ Kh, const __nv_bfloat16* __restrict__ Kl,
    const __nv_bfloat16* __restrict__ Vh, const __nv_bfloat16* __restrict__ Vl,
    __nv_bfloat16* __restrict__ Oh, __nv_bfloat16* __restrict__ Ol) {
    extern __shared__ char dsmem[];
    uint32_t sbQ = smem_u32(dsmem);
    uint32_t sbK = sbQ + 32768u;
    uint32_t sbV = sbK + 16384u;

    int tid = threadIdx.x;
    int wid = tid >> 5;
    int lane = tid & 31;
    int q0 = blockIdx.x * 128;
    int h = blockIdx.y;
    int b = blockIdx.z;

    const __nv_bfloat16* Qhg = Qh + ((size_t)(b * Tn + q0)) * Cn + h * HSn;
    const __nv_bfloat16* Qlg = Ql + ((size_t)(b * Tn + q0)) * Cn + h * HSn;
    const __nv_bfloat16* Khg = Kh + ((size_t)(b * Tn)) * Cn + h * HSn;
    const __nv_bfloat16* Klg = Kl + ((size_t)(b * Tn)) * Cn + h * HSn;
    const __nv_bfloat16* Vhg = Vh + ((size_t)(b * Tn)) * Cn + h * HSn;
    const __nv_bfloat16* Vlg = Vl + ((size_t)(b * Tn)) * Cn + h * HSn;

    // Q tile load (hi/lo), 128 rows x 64 cols, 128B rows, SW128
#pragma unroll
    for (int i = 0; i < 8; i++) {
        int g = i * 256 + tid;           // 0..2047
        int hilo = g >> 10;
        int idx = g & 1023;
        int row = idx >> 3;
        int ch = idx & 7;
        const __nv_bfloat16* src = (hilo ? Qlg : Qhg) + (size_t)row * Cn + ch * 8;
        CP_ASYNC16(sbQ + (uint32_t)hilo * 16384u + sw128((uint32_t)(row * 128 + ch * 16)), src);
    }

    auto load_kv = [&](int t) {
        int s0 = t * 64;
#pragma unroll
        for (int i = 0; i < 8; i++) {
            int g = i * 256 + tid;       // 0..2047
            int mat = g >> 9;            // 0 Kh, 1 Kl, 2 Vh, 3 Vl
            int idx = g & 511;
            int row = idx >> 3;
            int ch = idx & 7;
            const __nv_bfloat16* src;
            if (mat == 0)      src = Khg + (size_t)(s0 + row) * Cn + ch * 8;
            else if (mat == 1) src = Klg + (size_t)(s0 + row) * Cn + ch * 8;
            else if (mat == 2) src = Vhg + (size_t)(s0 + row) * Cn + ch * 8;
            else               src = Vlg + (size_t)(s0 + row) * Cn + ch * 8;
            uint32_t base = (mat < 2 ? sbK : sbV) + (uint32_t)(mat & 1) * 8192u;
            CP_ASYNC16(base + sw128((uint32_t)(row * 128 + ch * 16)), src);
        }
        CP_ASYNC_COMMIT();
    };

    float m0s = NEG_BIG, m1s = NEG_BIG, l0 = 0.f, l1 = 0.f;
    float co[8][4];
#pragma unroll
    for (int nt = 0; nt < 8; nt++)
#pragma unroll
        for (int j = 0; j < 4; j++) co[nt][j] = 0.f;

    int rw = q0 + wid * 16;
    int r0 = rw + (lane >> 2);
    int nkt = q0 / 64 + 2;
    const float scale = 0.125f;

    // ldmatrix lane address components
    int arow = lane & 15;
    int aoff = (lane >> 4) * 16;
    int brow = ((lane >> 4) << 3) + (lane & 7);
    int boff = ((lane >> 3) & 1) * 16;
    int vrow = ((lane >> 3) & 1) * 8 + (lane & 7);
    int vcol = (lane >> 4) * 8;

    for (int t = 0; t < nkt; t++) {
        load_kv(t);
        CP_ASYNC_WAIT0();
        __syncthreads();
        int s0 = t * 64;

        if (s0 <= rw + 15) {
            // ---- S = Q K^T (3-term) ----
            float sp[8][4];
#pragma unroll
            for (int nt = 0; nt < 8; nt++)
#pragma unroll
                for (int j = 0; j < 4; j++) sp[nt][j] = 0.f;

#pragma unroll
            for (int kk = 0; kk < 4; kk++) {
                uint32_t abyte = (uint32_t)((wid * 16 + arow) * 128 + kk * 32 + aoff);
                uint32_t aH[4], aL[4];
                ldsm4(aH, sbQ + sw128(abyte));
                ldsm4(aL, sbQ + 16384u + sw128(abyte));
#pragma unroll
                for (int nt16 = 0; nt16 < 4; nt16++) {
                    uint32_t bbyte = (uint32_t)((nt16 * 16 + brow) * 128 + kk * 32 + boff);
                    uint32_t bH[4], bL[4];
                    ldsm4(bH, sbK + sw128(bbyte));
                    ldsm4(bL, sbK + 8192u + sw128(bbyte));
#pragma unroll
                    for (int half = 0; half < 2; half++) {
                        int nt = nt16 * 2 + half;
                        mma16816(sp[nt], aH, bH[half * 2], bH[half * 2 + 1]);
                        mma16816(sp[nt], aH, bL[half * 2], bL[half * 2 + 1]);
                        mma16816(sp[nt], aL, bH[half * 2], bH[half * 2 + 1]);
                    }
                }
            }

            // ---- online softmax ----
            bool diag = (s0 + 63 > rw);
            float mx0 = NEG_BIG, mx1 = NEG_BIG;
#pragma unroll
            for (int nt = 0; nt < 8; nt++) {
                float c0 = sp[nt][0] * scale;
                float c1 = sp[nt][1] * scale;
                float c2 = sp[nt][2] * scale;
                float c3 = sp[nt][3] * scale;
                if (diag) {
                    int cg = s0 + nt * 8 + (lane & 3) * 2;
                    if (cg > r0) c0 = NEG_BIG;
                    if (cg + 1 > r0) c1 = NEG_BIG;
                    if (cg > r0 + 8) c2 = NEG_BIG;
                    if (cg + 1 > r0 + 8) c3 = NEG_BIG;
                }
                sp[nt][0] = c0; sp[nt][1] = c1; sp[nt][2] = c2; sp[nt][3] = c3;
                mx0 = fmaxf(mx0, fmaxf(c0, c1));
                mx1 = fmaxf(mx1, fmaxf(c2, c3));
            }
            mx0 = fmaxf(mx0, __shfl_xor_sync(0xffffffffu, mx0, 1));
            mx0 = fmaxf(mx0, __shfl_xor_sync(0xffffffffu, mx0, 2));
            mx1 = fmaxf(mx1, __shfl_xor_sync(0xffffffffu, mx1, 1));
            mx1 = fmaxf(mx1, __shfl_xor_sync(0xffffffffu, mx1, 2));

            float mn0 = fmaxf(m0s, mx0), mn1 = fmaxf(m1s, mx1);
            float al0 = __expf(m0s - mn0), al1 = __expf(m1s - mn1);
            m0s = mn0; m1s = mn1;

            float ps0 = 0.f, ps1 = 0.f;
#pragma unroll
            for (int nt = 0; nt < 8; nt++) {
                float p0 = __expf(sp[nt][0] - mn0);
                float p1 = __expf(sp[nt][1] - mn0);
                float p2 = __expf(sp[nt][2] - mn1);
                float p3 = __expf(sp[nt][3] - mn1);
                ps0 += p0 + p1; ps1 += p2 + p3;
                sp[nt][0] = p0; sp[nt][1] = p1; sp[nt][2] = p2; sp[nt][3] = p3;
            }
            ps0 += __shfl_xor_sync(0xffffffffu, ps0, 1);
            ps0 += __shfl_xor_sync(0xffffffffu, ps0, 2);
            ps1 += __shfl_xor_sync(0xffffffffu, ps1, 1);
            ps1 += __shfl_xor_sync(0xffffffffu, ps1, 2);
            l0 = l0 * al0 + ps0;
            l1 = l1 * al1 + ps1;
#pragma unroll
            for (int nt = 0; nt < 8; nt++) {
                co[nt][0] *= al0; co[nt][1] *= al0;
                co[nt][2] *= al1; co[nt][3] *= al1;
            }

            // ---- PV (3-term); P frags remapped from C layout ----
#pragma unroll
            for (int kk = 0; kk < 4; kk++) {
                uint32_t aPh[4], aPl[4];
#pragma unroll
                for (int q = 0; q < 2; q++) {       // two n-tiles forming k16
                    int nt = 2 * kk + q;
#pragma unroll
                    for (int rr = 0; rr < 2; rr++) {  // row / row+8 halves
                        float v0 = sp[nt][rr * 2 + 0];
                        float v1 = sp[nt][rr * 2 + 1];
                        __nv_bfloat162 hp = __floats2bfloat162_rn(v0, v1);
                        float r0f = v0 - __bfloat162float(hp.x);
                        float r1f = v1 - __bfloat162float(hp.y);
                        __nv_bfloat162 lp = __floats2bfloat162_rn(r0f, r1f);
                        aPh[q * 2 + rr] = *(uint32_t*)&hp;
                        aPl[q * 2 + rr] = *(uint32_t*)&lp;
                    }
                }
#pragma unroll
                for (int dnt16 = 0; dnt16 < 4; dnt16++) {
                    uint32_t vbyte = (uint32_t)((kk * 16 + vrow) * 128 + (dnt16 * 16 + vcol) * 2);
                    uint32_t vH[4], vL[4];
                    ldsm4t(vH, sbV + sw128(vbyte));
                    ldsm4t(vL, sbV + 8192u + sw128(vbyte));
#pragma unroll
                    for (int half = 0; half < 2; half++) {
                        int dn = dnt16 * 2 + half;
                        mma16816(co[dn], aPh, vH[half * 2], vH[half * 2 + 1]);
                        mma16816(co[dn], aPh, vL[half * 2], vL[half * 2 + 1]);
                        mma16816(co[dn], aPl, vH[half * 2], vH[half * 2 + 1]);
                    }
                }
            }
        }
        __syncthreads();
    }

    // ---- epilogue: normalize, split bf16, write [B,T,H,HS] ----
    float inv0 = 1.f / l0, inv1 = 1.f / l1;
#pragma unroll
    for (int dn = 0; dn < 8; dn++) {
        int d = h * HSn + dn * 8 + (lane & 3) * 2;
#pragma unroll
        for (int half = 0; half < 2; half++) {
            int row = r0 + half * 8;
            float inv = half ? inv1 : inv0;
            float v0 = co[dn][half * 2 + 0] * inv;
            float v1 = co[dn][half * 2 + 1] * inv;
            __nv_bfloat162 hp = __floats2bfloat162_rn(v0, v1);
            __nv_bfloat162 lp = __floats2bfloat162_rn(v0 - __bfloat162float(hp.x),
                                                      v1 - __bfloat162float(hp.y));
            size_t base = ((size_t)(b * Tn + row)) * Cn + d;
            *(__nv_bfloat162*)&Oh[base] = hp;
            *(__nv_bfloat162*)&Ol[base] = lp;
        }
    }
}

// ===========================================================================
// LayerNorm: fp32 out, or bf16 hi/lo split out
// ===========================================================================
template <bool SPLIT>
__global__ void ln_kernel(const float* __restrict__ X, const float* __restrict__ g,
                          const float* __restrict__ be, float* __restrict__ Y,
                          __nv_bfloat16* __restrict__ Yh, __nv_bfloat16* __restrict__ Yl) {
    int row = blockIdx.x;
    int tid = threadIdx.x;
    const float* xr = X + (size_t)row * Cn;

    float v[4];
    float s = 0.f, ss = 0.f;
#pragma unroll
    for (int i = 0; i < 4; i++) {
        v[i] = xr[tid + i * 256];
        s += v[i];
        ss += v[i] * v[i];
    }

    __shared__ float rs[256], rss[256];
    rs[tid] = s;
    rss[tid] = ss;
    __syncthreads();
    for (int off = 128; off; off >>= 1) {
        if (tid < off) {
            rs[tid] += rs[tid + off];
            rss[tid] += rss[tid + off];
        }
        __syncthreads();
    }
    float mean = rs[0] * (1.f / Cn);
    float var = rss[0] * (1.f / Cn) - mean * mean;
    float rstd = rsqrtf(var + EPSn);

#pragma unroll
    for (int i = 0; i < 4; i++) {
        int ccol = tid + i * 256;
        float y = (v[i] - mean) * rstd * g[ccol] + be[ccol];
        if (SPLIT) {
            __nv_bfloat16 hh = __float2bfloat16(y);
            Yh[(size_t)row * Cn + ccol] = hh;
            Yl[(size_t)row * Cn + ccol] = __float2bfloat16(y - __bfloat162float(hh));
        } else {
            Y[(size_t)row * Cn + ccol] = y;
        }
    }
}

// ===========================================================================
// Launch
// ===========================================================================
static float* symaddrf(const void* sym) {
    void* p = nullptr;
    cudaGetSymbolAddress(&p, sym);
    return (float*)p;
}
static __nv_bfloat16* symaddrb(const void* sym) {
    void* p = nullptr;
    cudaGetSymbolAddress(&p, sym);
    return (__nv_bfloat16*)p;
}

extern "C" void kernel_launch(void* const* d_in, const int* in_sizes, int n_in,
                              void* d_out, int out_size) {
    const float* x   = (const float*)d_in[0];
    const float* Wq  = (const float*)d_in[1];
    const float* bq  = (const float*)d_in[2];
    const float* Wk  = (const float*)d_in[3];
    const float* bk  = (const float*)d_in[4];
    const float* Wv  = (const float*)d_in[5];
    const float* bv  = (const float*)d_in[6];
    const float* Wp  = (const float*)d_in[7];
    const float* bp  = (const float*)d_in[8];
    const float* W1  = (const float*)d_in[9];
    const float* b1  = (const float*)d_in[10];
    const float* W2  = (const float*)d_in[11];
    const float* b2  = (const float*)d_in[12];
    const float* g1  = (const float*)d_in[13];
    const float* be1 = (const float*)d_in[14];
    const float* g2  = (const float*)d_in[15];
    const float* be2 = (const float*)d_in[16];
    float* out = (float*)d_out;

    __nv_bfloat16 *xh = symaddrb(g_xh), *xl = symaddrb(g_xl);
    __nv_bfloat16 *Wqth = symaddrb(g_Wqth), *Wqtl = symaddrb(g_Wqtl);
    __nv_bfloat16 *Wkth = symaddrb(g_Wkth), *Wktl = symaddrb(g_Wktl);
    __nv_bfloat16 *Wvth = symaddrb(g_Wvth), *Wvtl = symaddrb(g_Wvtl);
    __nv_bfloat16 *Wpth = symaddrb(g_Wpth), *Wptl = symaddrb(g_Wptl);
    __nv_bfloat16 *W1th = symaddrb(g_W1th), *W1tl = symaddrb(g_W1tl);
    __nv_bfloat16 *W2th = symaddrb(g_W2th), *W2tl = symaddrb(g_W2tl);
    __nv_bfloat16 *qh = symaddrb(g_qh), *ql = symaddrb(g_ql);
    __nv_bfloat16 *kh = symaddrb(g_kh), *kl = symaddrb(g_kl);
    __nv_bfloat16 *vh = symaddrb(g_vh), *vl = symaddrb(g_vl);
    __nv_bfloat16 *atth = symaddrb(g_atth), *attl = symaddrb(g_attl);
    __nv_bfloat16 *hh = symaddrb(g_hh), *hl = symaddrb(g_hl);
    __nv_bfloat16 *f1h = symaddrb(g_f1h), *f1l = symaddrb(g_f1l);
    float *t0 = symaddrf(g_t0), *f2 = symaddrf(g_f2);

    cudaFuncSetAttribute(gemm_mma<false, false>, cudaFuncAttributeMaxDynamicSharedMemorySize, GEMM_SMEM);
    cudaFuncSetAttribute(gemm_mma<true, false>,  cudaFuncAttributeMaxDynamicSharedMemorySize, GEMM_SMEM);
    cudaFuncSetAttribute(gemm_mma<true, true>,   cudaFuncAttributeMaxDynamicSharedMemorySize, GEMM_SMEM);
    cudaFuncSetAttribute(gemm_mma<false, true>,  cudaFuncAttributeMaxDynamicSharedMemorySize, GEMM_SMEM);
    cudaFuncSetAttribute(attn_mma, cudaFuncAttributeMaxDynamicSharedMemorySize, ATT_SMEM);

    const int M = Mrows;
    dim3 tb(32, 8);

    // 1) split x, transpose+split weights
    split_kernel<<<(M * Cn) / 256, 256>>>(x, xh, xl);
    transpose_split<<<dim3(HSn / 32, Cn / 32, Hn), tb>>>(Wq, Wqth, Wqtl, Cn, HSn);
    transpose_split<<<dim3(HSn / 32, Cn / 32, Hn), tb>>>(Wk, Wkth, Wktl, Cn, HSn);
    transpose_split<<<dim3(HSn / 32, Cn / 32, Hn), tb>>>(Wv, Wvth, Wvtl, Cn, HSn);
    transpose_split<<<dim3(Cn / 32, Cn / 32, 1), tb>>>(Wp, Wpth, Wptl, Cn, Cn);
    transpose_split<<<dim3(FFn / 32, Cn / 32, 1), tb>>>(W1, W1th, W1tl, Cn, FFn);
    transpose_split<<<dim3(Cn / 32, FFn / 32, 1), tb>>>(W2, W2th, W2tl, FFn, Cn);

    // 2) QKV projections -> split bf16 outputs
    gemm_mma<true, false><<<dim3(Cn / 128, M / 128), 256, GEMM_SMEM>>>(
        xh, xl, Wqth, Wqtl, bq, nullptr, qh, ql, M, Cn, Cn);
    gemm_mma<true, false><<<dim3(Cn / 128, M / 128), 256, GEMM_SMEM>>>(
        xh, xl, Wkth, Wktl, bk, nullptr, kh, kl, M, Cn, Cn);
    gemm_mma<true, false><<<dim3(Cn / 128, M / 128), 256, GEMM_SMEM>>>(
        xh, xl, Wvth, Wvtl, bv, nullptr, vh, vl, M, Cn, Cn);

    // 3) tensor-core flash attention
    attn_mma<<<dim3(Tn / 128, Hn, Bn), 256, ATT_SMEM>>>(
        qh, ql, kh, kl, vh, vl, atth, attl);

    // 4) output projection
    gemm_mma<false, false><<<dim3(Cn / 128, M / 128), 256, GEMM_SMEM>>>(
        atth, attl, Wpth, Wptl, bp, t0, nullptr, nullptr, M, Cn, Cn);

    // 5) LN1 -> split
    ln_kernel<true><<<M, 256>>>(t0, g1, be1, nullptr, hh, hl);

    // 6) FFN
    gemm_mma<true, true><<<dim3(FFn / 128, M / 128), 256, GEMM_SMEM>>>(
        hh, hl, W1th, W1tl, b1, nullptr, f1h, f1l, M, FFn, Cn);
    gemm_mma<false, true><<<dim3(Cn / 128, M / 128), 256, GEMM_SMEM>>>(
        f1h, f1l, W2th, W2tl, b2, f2, nullptr, nullptr, M, Cn, FFn);

    // 7) LN2 -> output
    ln_kernel<false><<<M, 256>>>(f2, g2, be2, out, nullptr, nullptr);
}

// round 6
// speedup vs baseline: 6.9997x; 1.1213x over previous
#include <cuda_runtime.h>
#include <cuda_bf16.h>
#include <math.h>
#include <stdint.h>

// Problem constants
#define Bn 2
#define Tn 2048
#define Cn 1024
#define Hn 16
#define HSn 64
#define FFn 4096
#define EPSn 1e-5f
#define NEG_BIG (-1e30f)
#define Mrows (Bn * Tn)   // 4096
#define QKVS (3 * Cn)     // fused qkv row stride

// ===========================================================================
// PTX helpers (generic sm_80+ only)
// ===========================================================================
__device__ __forceinline__ uint32_t smem_u32(const void* p) {
    uint32_t a;
    asm("{ .reg .u64 t; cvta.to.shared.u64 t, %1; cvt.u32.u64 %0, t; }" : "=r"(a) : "l"(p));
    return a;
}

#define CP_ASYNC16(dst, src) \
    asm volatile("cp.async.cg.shared.global [%0], [%1], 16;" :: "r"(dst), "l"(src))
#define CP_ASYNC_COMMIT() asm volatile("cp.async.commit_group;" ::: "memory")
#define CP_ASYNC_WAIT0() asm volatile("cp.async.wait_group 0;" ::: "memory")
#define CP_ASYNC_WAIT1() asm volatile("cp.async.wait_group 1;" ::: "memory")

__device__ __forceinline__ void ldsm4(uint32_t r[4], uint32_t addr) {
    asm volatile("ldmatrix.sync.aligned.m8n8.x4.shared.b16 {%0,%1,%2,%3}, [%4];"
                 : "=r"(r[0]), "=r"(r[1]), "=r"(r[2]), "=r"(r[3]) : "r"(addr));
}
__device__ __forceinline__ void ldsm4t(uint32_t r[4], uint32_t addr) {
    asm volatile("ldmatrix.sync.aligned.m8n8.x4.trans.shared.b16 {%0,%1,%2,%3}, [%4];"
                 : "=r"(r[0]), "=r"(r[1]), "=r"(r[2]), "=r"(r[3]) : "r"(addr));
}

__device__ __forceinline__ void mma16816(float c[4], const uint32_t a[4],
                                         uint32_t b0, uint32_t b1) {
    asm volatile(
        "mma.sync.aligned.m16n8k16.row.col.f32.bf16.bf16.f32 "
        "{%0,%1,%2,%3}, {%4,%5,%6,%7}, {%8,%9}, {%0,%1,%2,%3};"
        : "+f"(c[0]), "+f"(c[1]), "+f"(c[2]), "+f"(c[3])
        : "r"(a[0]), "r"(a[1]), "r"(a[2]), "r"(a[3]), "r"(b0), "r"(b1));
}

__device__ __forceinline__ uint32_t sw64(uint32_t b) { return b ^ ((b >> 3) & 0x30u); }
__device__ __forceinline__ uint32_t sw128(uint32_t b) { return b ^ ((b >> 3) & 0x70u); }

// ===========================================================================
// Device scratch
// ===========================================================================
__device__ __align__(256) __nv_bfloat16 g_xh[Mrows * Cn], g_xl[Mrows * Cn];
__device__ __align__(256) __nv_bfloat16 g_Wqkvth[3 * Cn * Cn], g_Wqkvtl[3 * Cn * Cn];
__device__ __align__(256) __nv_bfloat16 g_Wpth[Cn * Cn], g_Wptl[Cn * Cn];
__device__ __align__(256) __nv_bfloat16 g_W1th[FFn * Cn], g_W1tl[FFn * Cn];
__device__ __align__(256) __nv_bfloat16 g_W2th[Cn * FFn], g_W2tl[Cn * FFn];
__device__ __align__(256) float g_bqkv[3 * Cn];
__device__ __align__(256) __nv_bfloat16 g_qkvh[Mrows * 3 * Cn], g_qkvl[Mrows * 3 * Cn];
__device__ __align__(256) __nv_bfloat16 g_atth[Mrows * Cn], g_attl[Mrows * Cn];
__device__ __align__(256) __nv_bfloat16 g_hh[Mrows * Cn], g_hl[Mrows * Cn];
__device__ __align__(256) __nv_bfloat16 g_f1h[Mrows * FFn], g_f1l[Mrows * FFn];
__device__ __align__(256) float g_t0[Mrows * Cn];
__device__ __align__(256) float g_f2[Mrows * Cn];

// ===========================================================================
// Elementwise split: fp32 -> (hi, lo) bf16
// ===========================================================================
__global__ void split_kernel(const float* __restrict__ in, __nv_bfloat16* __restrict__ oh,
                             __nv_bfloat16* __restrict__ ol) {
    int i = blockIdx.x * 256 + threadIdx.x;
    float v = in[i];
    __nv_bfloat16 h = __float2bfloat16(v);
    oh[i] = h;
    ol[i] = __float2bfloat16(v - __bfloat162float(h));
}

// Concat qkv biases into one [3072] buffer
__global__ void bias_concat(const float* __restrict__ bq, const float* __restrict__ bk,
                            const float* __restrict__ bv, float* __restrict__ o) {
    int i = blockIdx.x * 256 + threadIdx.x;   // 0..3071
    float v = (i < Cn) ? bq[i] : (i < 2 * Cn) ? bk[i - Cn] : bv[i - 2 * Cn];
    o[i] = v;
}

// ===========================================================================
// Tiled transpose+split: in [R, Cc] fp32 per z-batch -> out [Cc, R] bf16 hi/lo
// ===========================================================================
__global__ void transpose_split(const float* __restrict__ in, __nv_bfloat16* __restrict__ oh,
                                __nv_bfloat16* __restrict__ ol, int R, int Cc) {
    __shared__ float tile[32][33];
    size_t boff = (size_t)blockIdx.z * R * Cc;
    const float* ip = in + boff;
    int i0 = blockIdx.y * 32, j0 = blockIdx.x * 32;
#pragma unroll
    for (int k = threadIdx.y; k < 32; k += 8)
        tile[k][threadIdx.x] = ip[(size_t)(i0 + k) * Cc + j0 + threadIdx.x];
    __syncthreads();
#pragma unroll
    for (int k = threadIdx.y; k < 32; k += 8) {
        float v = tile[threadIdx.x][k];
        __nv_bfloat16 h = __float2bfloat16(v);
        size_t o = boff + (size_t)(j0 + k) * R + i0 + threadIdx.x;
        oh[o] = h;
        ol[o] = __float2bfloat16(v - __bfloat162float(h));
    }
}

// ===========================================================================
// Tensor-core GEMM via mma.sync, bf16 hi/lo split operands (3-term fp32 emu).
// CTA 128x128, 8 warps (4Mx2N), warp tile 32x64, K-chunk 32, 3-stage cp.async.
// Occupancy 2 CTAs/SM (regs <= 128, smem 96KB*2 = 192KB).
// ===========================================================================
#define STAGE_BYTES 32768
#define GEMM_SMEM (3 * STAGE_BYTES)

template <bool SPLIT, bool RELU>
__global__ void __launch_bounds__(256, 2)
gemm_mma(const __nv_bfloat16* __restrict__ Ahi, const __nv_bfloat16* __restrict__ Alo,
         const __nv_bfloat16* __restrict__ Bhi, const __nv_bfloat16* __restrict__ Blo,
         const float* __restrict__ bias,
         float* __restrict__ Cf, __nv_bfloat16* __restrict__ Chi, __nv_bfloat16* __restrict__ Clo,
         int M, int N, int K) {
    extern __shared__ char dsmem[];
    uint32_t sb = smem_u32(dsmem);

    int tid = threadIdx.x;
    int wid = tid >> 5;
    int lane = tid & 31;
    int n0 = blockIdx.x * 128;
    int m0 = blockIdx.y * 128;
    int wm = wid & 3;
    int wn = wid >> 2;

    const int NC = K >> 5;

    auto load_chunk = [&](int c, int stage) {
        uint32_t base = sb + (uint32_t)stage * STAGE_BYTES;
        size_t kof = (size_t)c * 32;
#pragma unroll
        for (int i = 0; i < 8; i++) {
            int g = i * 256 + tid;
            int tilei = g >> 9;
            int idx = g & 511;
            int row = idx >> 2;
            int ch = idx & 3;
            const __nv_bfloat16* src;
            if (tilei == 0)      src = Ahi + (size_t)(m0 + row) * K + kof + ch * 8;
            else if (tilei == 1) src = Alo + (size_t)(m0 + row) * K + kof + ch * 8;
            else if (tilei == 2) src = Bhi + (size_t)(n0 + row) * K + kof + ch * 8;
            else                 src = Blo + (size_t)(n0 + row) * K + kof + ch * 8;
            uint32_t dst = base + (uint32_t)tilei * 8192u + sw64((uint32_t)(row * 64 + ch * 16));
            CP_ASYNC16(dst, src);
        }
        CP_ASYNC_COMMIT();
    };

    float c[2][8][4];
#pragma unroll
    for (int mt = 0; mt < 2; mt++)
#pragma unroll
        for (int nt = 0; nt < 8; nt++)
#pragma unroll
            for (int j = 0; j < 4; j++) c[mt][nt][j] = 0.f;

    load_chunk(0, 0);
    load_chunk(1, 1);

    int arow = lane & 15;
    int aoff = (lane >> 4) * 16;
    int brow = ((lane >> 4) << 3) + (lane & 7);
    int boff = ((lane >> 3) & 1) * 16;

    for (int cc = 0; cc < NC; cc++) {
        if (cc == NC - 1) { CP_ASYNC_WAIT0(); } else { CP_ASYNC_WAIT1(); }
        __syncthreads();
        if (cc + 2 < NC) load_chunk(cc + 2, (cc + 2) % 3);

        uint32_t base = sb + (uint32_t)(cc % 3) * STAGE_BYTES;
#pragma unroll
        for (int k16 = 0; k16 < 2; k16++) {
            uint32_t ahi[2][4], alo[2][4];
#pragma unroll
            for (int mt = 0; mt < 2; mt++) {
                uint32_t byte = (uint32_t)((wm * 32 + mt * 16 + arow) * 64 + k16 * 32 + aoff);
                uint32_t sw = sw64(byte);
                ldsm4(ahi[mt], base + sw);
                ldsm4(alo[mt], base + 8192u + sw);
            }
            // consume B per nt16 tile to keep live registers <= 128
#pragma unroll
            for (int nt16 = 0; nt16 < 4; nt16++) {
                uint32_t byte = (uint32_t)((wn * 64 + nt16 * 16 + brow) * 64 + k16 * 32 + boff);
                uint32_t sw = sw64(byte);
                uint32_t bh[4], bl[4];
                ldsm4(bh, base + 16384u + sw);
                ldsm4(bl, base + 24576u + sw);
#pragma unroll
                for (int half = 0; half < 2; half++) {
                    int nt = nt16 * 2 + half;
#pragma unroll
                    for (int mt = 0; mt < 2; mt++) {
                        mma16816(c[mt][nt], ahi[mt], bh[half * 2], bh[half * 2 + 1]);
                        mma16816(c[mt][nt], ahi[mt], bl[half * 2], bl[half * 2 + 1]);
                        mma16816(c[mt][nt], alo[mt], bh[half * 2], bh[half * 2 + 1]);
                    }
                }
            }
        }
    }

    int mbase = m0 + wm * 32;
    int nbase = n0 + wn * 64;
#pragma unroll
    for (int mt = 0; mt < 2; mt++) {
#pragma unroll
        for (int nt = 0; nt < 8; nt++) {
            int row0 = mbase + mt * 16 + (lane >> 2);
            int col = nbase + nt * 8 + (lane & 3) * 2;
            float b0 = bias[col], b1 = bias[col + 1];
#pragma unroll
            for (int half = 0; half < 2; half++) {
                int row = row0 + half * 8;
                float v0 = c[mt][nt][half * 2 + 0] + b0;
                float v1 = c[mt][nt][half * 2 + 1] + b1;
                if (RELU) { v0 = fmaxf(v0, 0.f); v1 = fmaxf(v1, 0.f); }
                if (SPLIT) {
                    __nv_bfloat16 h0 = __float2bfloat16(v0);
                    __nv_bfloat16 h1 = __float2bfloat16(v1);
                    __nv_bfloat162 hp; hp.x = h0; hp.y = h1;
                    __nv_bfloat162 lp;
                    lp.x = __float2bfloat16(v0 - __bfloat162float(h0));
                    lp.y = __float2bfloat16(v1 - __bfloat162float(h1));
                    *(__nv_bfloat162*)&Chi[(size_t)row * N + col] = hp;
                    *(__nv_bfloat162*)&Clo[(size_t)row * N + col] = lp;
                } else {
                    float2 r; r.x = v0; r.y = v1;
                    *(float2*)&Cf[(size_t)row * N + col] = r;
                }
            }
        }
    }
}

// ===========================================================================
// Tensor-core flash attention with bf16 split emulation.
// Q/K/V read from fused [M, 3*Cn] buffer (row stride QKVS).
// ===========================================================================
#define ATT_SMEM 65536

__global__ void __launch_bounds__(256, 2) attn_mma(
    const __nv_bfloat16* __restrict__ QKVh, const __nv_bfloat16* __restrict__ QKVl,
    __nv_bfloat16* __restrict__ Oh, __nv_bfloat16* __restrict__ Ol) {
    extern __shared__ char dsmem[];
    uint32_t sbQ = smem_u32(dsmem);
    uint32_t sbK = sbQ + 32768u;
    uint32_t sbV = sbK + 16384u;

    int tid = threadIdx.x;
    int wid = tid >> 5;
    int lane = tid & 31;
    int q0 = blockIdx.x * 128;
    int h = blockIdx.y;
    int b = blockIdx.z;

    const __nv_bfloat16* Qhg = QKVh + ((size_t)(b * Tn + q0)) * QKVS + h * HSn;
    const __nv_bfloat16* Qlg = QKVl + ((size_t)(b * Tn + q0)) * QKVS + h * HSn;
    const __nv_bfloat16* Khg = QKVh + ((size_t)(b * Tn)) * QKVS + Cn + h * HSn;
    const __nv_bfloat16* Klg = QKVl + ((size_t)(b * Tn)) * QKVS + Cn + h * HSn;
    const __nv_bfloat16* Vhg = QKVh + ((size_t)(b * Tn)) * QKVS + 2 * Cn + h * HSn;
    const __nv_bfloat16* Vlg = QKVl + ((size_t)(b * Tn)) * QKVS + 2 * Cn + h * HSn;

    // Q tile load (hi/lo), 128 rows x 64 cols, 128B rows, SW128
#pragma unroll
    for (int i = 0; i < 8; i++) {
        int g = i * 256 + tid;
        int hilo = g >> 10;
        int idx = g & 1023;
        int row = idx >> 3;
        int ch = idx & 7;
        const __nv_bfloat16* src = (hilo ? Qlg : Qhg) + (size_t)row * QKVS + ch * 8;
        CP_ASYNC16(sbQ + (uint32_t)hilo * 16384u + sw128((uint32_t)(row * 128 + ch * 16)), src);
    }

    auto load_kv = [&](int t) {
        int s0 = t * 64;
#pragma unroll
        for (int i = 0; i < 8; i++) {
            int g = i * 256 + tid;
            int mat = g >> 9;
            int idx = g & 511;
            int row = idx >> 3;
            int ch = idx & 7;
            const __nv_bfloat16* src;
            if (mat == 0)      src = Khg + (size_t)(s0 + row) * QKVS + ch * 8;
            else if (mat == 1) src = Klg + (size_t)(s0 + row) * QKVS + ch * 8;
            else if (mat == 2) src = Vhg + (size_t)(s0 + row) * QKVS + ch * 8;
            else               src = Vlg + (size_t)(s0 + row) * QKVS + ch * 8;
            uint32_t base = (mat < 2 ? sbK : sbV) + (uint32_t)(mat & 1) * 8192u;
            CP_ASYNC16(base + sw128((uint32_t)(row * 128 + ch * 16)), src);
        }
        CP_ASYNC_COMMIT();
    };

    float m0s = NEG_BIG, m1s = NEG_BIG, l0 = 0.f, l1 = 0.f;
    float co[8][4];
#pragma unroll
    for (int nt = 0; nt < 8; nt++)
#pragma unroll
        for (int j = 0; j < 4; j++) co[nt][j] = 0.f;

    int rw = q0 + wid * 16;
    int r0 = rw + (lane >> 2);
    int nkt = q0 / 64 + 2;
    const float scale = 0.125f;

    int arow = lane & 15;
    int aoff = (lane >> 4) * 16;
    int brow = ((lane >> 4) << 3) + (lane & 7);
    int boff = ((lane >> 3) & 1) * 16;
    int vrow = ((lane >> 3) & 1) * 8 + (lane & 7);
    int vcol = (lane >> 4) * 8;

    for (int t = 0; t < nkt; t++) {
        load_kv(t);
        CP_ASYNC_WAIT0();
        __syncthreads();
        int s0 = t * 64;

        if (s0 <= rw + 15) {
            float sp[8][4];
#pragma unroll
            for (int nt = 0; nt < 8; nt++)
#pragma unroll
                for (int j = 0; j < 4; j++) sp[nt][j] = 0.f;

#pragma unroll
            for (int kk = 0; kk < 4; kk++) {
                uint32_t abyte = (uint32_t)((wid * 16 + arow) * 128 + kk * 32 + aoff);
                uint32_t aH[4], aL[4];
                ldsm4(aH, sbQ + sw128(abyte));
                ldsm4(aL, sbQ + 16384u + sw128(abyte));
#pragma unroll
                for (int nt16 = 0; nt16 < 4; nt16++) {
                    uint32_t bbyte = (uint32_t)((nt16 * 16 + brow) * 128 + kk * 32 + boff);
                    uint32_t bH[4], bL[4];
                    ldsm4(bH, sbK + sw128(bbyte));
                    ldsm4(bL, sbK + 8192u + sw128(bbyte));
#pragma unroll
                    for (int half = 0; half < 2; half++) {
                        int nt = nt16 * 2 + half;
                        mma16816(sp[nt], aH, bH[half * 2], bH[half * 2 + 1]);
                        mma16816(sp[nt], aH, bL[half * 2], bL[half * 2 + 1]);
                        mma16816(sp[nt], aL, bH[half * 2], bH[half * 2 + 1]);
                    }
                }
            }

            bool diag = (s0 + 63 > rw);
            float mx0 = NEG_BIG, mx1 = NEG_BIG;
#pragma unroll
            for (int nt = 0; nt < 8; nt++) {
                float c0 = sp[nt][0] * scale;
                float c1 = sp[nt][1] * scale;
                float c2 = sp[nt][2] * scale;
                float c3 = sp[nt][3] * scale;
                if (diag) {
                    int cg = s0 + nt * 8 + (lane & 3) * 2;
                    if (cg > r0) c0 = NEG_BIG;
                    if (cg + 1 > r0) c1 = NEG_BIG;
                    if (cg > r0 + 8) c2 = NEG_BIG;
                    if (cg + 1 > r0 + 8) c3 = NEG_BIG;
                }
                sp[nt][0] = c0; sp[nt][1] = c1; sp[nt][2] = c2; sp[nt][3] = c3;
                mx0 = fmaxf(mx0, fmaxf(c0, c1));
                mx1 = fmaxf(mx1, fmaxf(c2, c3));
            }
            mx0 = fmaxf(mx0, __shfl_xor_sync(0xffffffffu, mx0, 1));
            mx0 = fmaxf(mx0, __shfl_xor_sync(0xffffffffu, mx0, 2));
            mx1 = fmaxf(mx1, __shfl_xor_sync(0xffffffffu, mx1, 1));
            mx1 = fmaxf(mx1, __shfl_xor_sync(0xffffffffu, mx1, 2));

            float mn0 = fmaxf(m0s, mx0), mn1 = fmaxf(m1s, mx1);
            float al0 = __expf(m0s - mn0), al1 = __expf(m1s - mn1);
            m0s = mn0; m1s = mn1;

            float ps0 = 0.f, ps1 = 0.f;
#pragma unroll
            for (int nt = 0; nt < 8; nt++) {
                float p0 = __expf(sp[nt][0] - mn0);
                float p1 = __expf(sp[nt][1] - mn0);
                float p2 = __expf(sp[nt][2] - mn1);
                float p3 = __expf(sp[nt][3] - mn1);
                ps0 += p0 + p1; ps1 += p2 + p3;
                sp[nt][0] = p0; sp[nt][1] = p1; sp[nt][2] = p2; sp[nt][3] = p3;
            }
            ps0 += __shfl_xor_sync(0xffffffffu, ps0, 1);
            ps0 += __shfl_xor_sync(0xffffffffu, ps0, 2);
            ps1 += __shfl_xor_sync(0xffffffffu, ps1, 1);
            ps1 += __shfl_xor_sync(0xffffffffu, ps1, 2);
            l0 = l0 * al0 + ps0;
            l1 = l1 * al1 + ps1;
#pragma unroll
            for (int nt = 0; nt < 8; nt++) {
                co[nt][0] *= al0; co[nt][1] *= al0;
                co[nt][2] *= al1; co[nt][3] *= al1;
            }

#pragma unroll
            for (int kk = 0; kk < 4; kk++) {
                uint32_t aPh[4], aPl[4];
#pragma unroll
                for (int q = 0; q < 2; q++) {
                    int nt = 2 * kk + q;
#pragma unroll
                    for (int rr = 0; rr < 2; rr++) {
                        float v0 = sp[nt][rr * 2 + 0];
                        float v1 = sp[nt][rr * 2 + 1];
                        __nv_bfloat162 hp = __floats2bfloat162_rn(v0, v1);
                        float r0f = v0 - __bfloat162float(hp.x);
                        float r1f = v1 - __bfloat162float(hp.y);
                        __nv_bfloat162 lp = __floats2bfloat162_rn(r0f, r1f);
                        aPh[q * 2 + rr] = *(uint32_t*)&hp;
                        aPl[q * 2 + rr] = *(uint32_t*)&lp;
                    }
                }
#pragma unroll
                for (int dnt16 = 0; dnt16 < 4; dnt16++) {
                    uint32_t vbyte = (uint32_t)((kk * 16 + vrow) * 128 + (dnt16 * 16 + vcol) * 2);
                    uint32_t vH[4], vL[4];
                    ldsm4t(vH, sbV + sw128(vbyte));
                    ldsm4t(vL, sbV + 8192u + sw128(vbyte));
#pragma unroll
                    for (int half = 0; half < 2; half++) {
                        int dn = dnt16 * 2 + half;
                        mma16816(co[dn], aPh, vH[half * 2], vH[half * 2 + 1]);
                        mma16816(co[dn], aPh, vL[half * 2], vL[half * 2 + 1]);
                        mma16816(co[dn], aPl, vH[half * 2], vH[half * 2 + 1]);
                    }
                }
            }
        }
        __syncthreads();
    }

    float inv0 = 1.f / l0, inv1 = 1.f / l1;
#pragma unroll
    for (int dn = 0; dn < 8; dn++) {
        int d = h * HSn + dn * 8 + (lane & 3) * 2;
#pragma unroll
        for (int half = 0; half < 2; half++) {
            int row = r0 + half * 8;
            float inv = half ? inv1 : inv0;
            float v0 = co[dn][half * 2 + 0] * inv;
            float v1 = co[dn][half * 2 + 1] * inv;
            __nv_bfloat162 hp = __floats2bfloat162_rn(v0, v1);
            __nv_bfloat162 lp = __floats2bfloat162_rn(v0 - __bfloat162float(hp.x),
                                                      v1 - __bfloat162float(hp.y));
            size_t base = ((size_t)(b * Tn + row)) * Cn + d;
            *(__nv_bfloat162*)&Oh[base] = hp;
            *(__nv_bfloat162*)&Ol[base] = lp;
        }
    }
}

// ===========================================================================
// LayerNorm: fp32 out, or bf16 hi/lo split out
// ===========================================================================
template <bool SPLIT>
__global__ void ln_kernel(const float* __restrict__ X, const float* __restrict__ g,
                          const float* __restrict__ be, float* __restrict__ Y,
                          __nv_bfloat16* __restrict__ Yh, __nv_bfloat16* __restrict__ Yl) {
    int row = blockIdx.x;
    int tid = threadIdx.x;
    const float* xr = X + (size_t)row * Cn;

    float v[4];
    float s = 0.f, ss = 0.f;
#pragma unroll
    for (int i = 0; i < 4; i++) {
        v[i] = xr[tid + i * 256];
        s += v[i];
        ss += v[i] * v[i];
    }

    __shared__ float rs[256], rss[256];
    rs[tid] = s;
    rss[tid] = ss;
    __syncthreads();
    for (int off = 128; off; off >>= 1) {
        if (tid < off) {
            rs[tid] += rs[tid + off];
            rss[tid] += rss[tid + off];
        }
        __syncthreads();
    }
    float mean = rs[0] * (1.f / Cn);
    float var = rss[0] * (1.f / Cn) - mean * mean;
    float rstd = rsqrtf(var + EPSn);

#pragma unroll
    for (int i = 0; i < 4; i++) {
        int ccol = tid + i * 256;
        float y = (v[i] - mean) * rstd * g[ccol] + be[ccol];
        if (SPLIT) {
            __nv_bfloat16 hh = __float2bfloat16(y);
            Yh[(size_t)row * Cn + ccol] = hh;
            Yl[(size_t)row * Cn + ccol] = __float2bfloat16(y - __bfloat162float(hh));
        } else {
            Y[(size_t)row * Cn + ccol] = y;
        }
    }
}

// ===========================================================================
// Launch
// ===========================================================================
static float* symaddrf(const void* sym) {
    void* p = nullptr;
    cudaGetSymbolAddress(&p, sym);
    return (float*)p;
}
static __nv_bfloat16* symaddrb(const void* sym) {
    void* p = nullptr;
    cudaGetSymbolAddress(&p, sym);
    return (__nv_bfloat16*)p;
}

extern "C" void kernel_launch(void* const* d_in, const int* in_sizes, int n_in,
                              void* d_out, int out_size) {
    const float* x   = (const float*)d_in[0];
    const float* Wq  = (const float*)d_in[1];
    const float* bq  = (const float*)d_in[2];
    const float* Wk  = (const float*)d_in[3];
    const float* bk  = (const float*)d_in[4];
    const float* Wv  = (const float*)d_in[5];
    const float* bv  = (const float*)d_in[6];
    const float* Wp  = (const float*)d_in[7];
    const float* bp  = (const float*)d_in[8];
    const float* W1  = (const float*)d_in[9];
    const float* b1  = (const float*)d_in[10];
    const float* W2  = (const float*)d_in[11];
    const float* b2  = (const float*)d_in[12];
    const float* g1  = (const float*)d_in[13];
    const float* be1 = (const float*)d_in[14];
    const float* g2  = (const float*)d_in[15];
    const float* be2 = (const float*)d_in[16];
    float* out = (float*)d_out;

    __nv_bfloat16 *xh = symaddrb(g_xh), *xl = symaddrb(g_xl);
    __nv_bfloat16 *Wqkvth = symaddrb(g_Wqkvth), *Wqkvtl = symaddrb(g_Wqkvtl);
    __nv_bfloat16 *Wpth = symaddrb(g_Wpth), *Wptl = symaddrb(g_Wptl);
    __nv_bfloat16 *W1th = symaddrb(g_W1th), *W1tl = symaddrb(g_W1tl);
    __nv_bfloat16 *W2th = symaddrb(g_W2th), *W2tl = symaddrb(g_W2tl);
    __nv_bfloat16 *qkvh = symaddrb(g_qkvh), *qkvl = symaddrb(g_qkvl);
    __nv_bfloat16 *atth = symaddrb(g_atth), *attl = symaddrb(g_attl);
    __nv_bfloat16 *hh = symaddrb(g_hh), *hl = symaddrb(g_hl);
    __nv_bfloat16 *f1h = symaddrb(g_f1h), *f1l = symaddrb(g_f1l);
    float *bqkv = symaddrf(g_bqkv);
    float *t0 = symaddrf(g_t0), *f2 = symaddrf(g_f2);

    cudaFuncSetAttribute(gemm_mma<false, false>, cudaFuncAttributeMaxDynamicSharedMemorySize, GEMM_SMEM);
    cudaFuncSetAttribute(gemm_mma<true, false>,  cudaFuncAttributeMaxDynamicSharedMemorySize, GEMM_SMEM);
    cudaFuncSetAttribute(gemm_mma<true, true>,   cudaFuncAttributeMaxDynamicSharedMemorySize, GEMM_SMEM);
    cudaFuncSetAttribute(gemm_mma<false, true>,  cudaFuncAttributeMaxDynamicSharedMemorySize, GEMM_SMEM);
    cudaFuncSetAttribute(attn_mma, cudaFuncAttributeMaxDynamicSharedMemorySize, ATT_SMEM);

    const int M = Mrows;
    dim3 tb(32, 8);

    // 1) split x; transpose+split weights; concat qkv bias
    split_kernel<<<(M * Cn) / 256, 256>>>(x, xh, xl);
    transpose_split<<<dim3(HSn / 32, Cn / 32, Hn), tb>>>(Wq, Wqkvth, Wqkvtl, Cn, HSn);
    transpose_split<<<dim3(HSn / 32, Cn / 32, Hn), tb>>>(Wk, Wqkvth + Cn * Cn, Wqkvtl + Cn * Cn, Cn, HSn);
    transpose_split<<<dim3(HSn / 32, Cn / 32, Hn), tb>>>(Wv, Wqkvth + 2 * Cn * Cn, Wqkvtl + 2 * Cn * Cn, Cn, HSn);
    transpose_split<<<dim3(Cn / 32, Cn / 32, 1), tb>>>(Wp, Wpth, Wptl, Cn, Cn);
    transpose_split<<<dim3(FFn / 32, Cn / 32, 1), tb>>>(W1, W1th, W1tl, Cn, FFn);
    transpose_split<<<dim3(Cn / 32, FFn / 32, 1), tb>>>(W2, W2th, W2tl, FFn, Cn);
    bias_concat<<<(3 * Cn) / 256, 256>>>(bq, bk, bv, bqkv);

    // 2) fused QKV projection -> split bf16 [M, 3072]
    gemm_mma<true, false><<<dim3(3 * Cn / 128, M / 128), 256, GEMM_SMEM>>>(
        xh, xl, Wqkvth, Wqkvtl, bqkv, nullptr, qkvh, qkvl, M, 3 * Cn, Cn);

    // 3) tensor-core flash attention
    attn_mma<<<dim3(Tn / 128, Hn, Bn), 256, ATT_SMEM>>>(qkvh, qkvl, atth, attl);

    // 4) output projection
    gemm_mma<false, false><<<dim3(Cn / 128, M / 128), 256, GEMM_SMEM>>>(
        atth, attl, Wpth, Wptl, bp, t0, nullptr, nullptr, M, Cn, Cn);

    // 5) LN1 -> split
    ln_kernel<true><<<M, 256>>>(t0, g1, be1, nullptr, hh, hl);

    // 6) FFN
    gemm_mma<true, true><<<dim3(FFn / 128, M / 128), 256, GEMM_SMEM>>>(
        hh, hl, W1th, W1tl, b1, nullptr, f1h, f1l, M, FFn, Cn);
    gemm_mma<false, true><<<dim3(Cn / 128, M / 128), 256, GEMM_SMEM>>>(
        f1h, f1l, W2th, W2tl, b2, f2, nullptr, nullptr, M, Cn, FFn);

    // 7) LN2 -> output
    ln_kernel<false><<<M, 256>>>(f2, g2, be2, out, nullptr, nullptr);
}

// round 7
// speedup vs baseline: 7.0164x; 1.0024x over previous
#include <cuda_runtime.h>
#include <cuda_bf16.h>
#include <math.h>
#include <stdint.h>

// Problem constants
#define Bn 2
#define Tn 2048
#define Cn 1024
#define Hn 16
#define HSn 64
#define FFn 4096
#define EPSn 1e-5f
#define NEG_BIG (-1e30f)
#define Mrows (Bn * Tn)   // 4096
#define QKVS (3 * Cn)     // fused qkv row stride

// ===========================================================================
// PTX helpers (generic sm_80+ only)
// ===========================================================================
__device__ __forceinline__ uint32_t smem_u32(const void* p) {
    uint32_t a;
    asm("{ .reg .u64 t; cvta.to.shared.u64 t, %1; cvt.u32.u64 %0, t; }" : "=r"(a) : "l"(p));
    return a;
}

#define CP_ASYNC16(dst, src) \
    asm volatile("cp.async.cg.shared.global [%0], [%1], 16;" :: "r"(dst), "l"(src))
#define CP_ASYNC_COMMIT() asm volatile("cp.async.commit_group;" ::: "memory")
#define CP_ASYNC_WAIT0() asm volatile("cp.async.wait_group 0;" ::: "memory")
#define CP_ASYNC_WAIT1() asm volatile("cp.async.wait_group 1;" ::: "memory")

__device__ __forceinline__ void ldsm4(uint32_t r[4], uint32_t addr) {
    asm volatile("ldmatrix.sync.aligned.m8n8.x4.shared.b16 {%0,%1,%2,%3}, [%4];"
                 : "=r"(r[0]), "=r"(r[1]), "=r"(r[2]), "=r"(r[3]) : "r"(addr));
}
__device__ __forceinline__ void ldsm4t(uint32_t r[4], uint32_t addr) {
    asm volatile("ldmatrix.sync.aligned.m8n8.x4.trans.shared.b16 {%0,%1,%2,%3}, [%4];"
                 : "=r"(r[0]), "=r"(r[1]), "=r"(r[2]), "=r"(r[3]) : "r"(addr));
}

__device__ __forceinline__ void mma16816(float c[4], const uint32_t a[4],
                                         uint32_t b0, uint32_t b1) {
    asm volatile(
        "mma.sync.aligned.m16n8k16.row.col.f32.bf16.bf16.f32 "
        "{%0,%1,%2,%3}, {%4,%5,%6,%7}, {%8,%9}, {%0,%1,%2,%3};"
        : "+f"(c[0]), "+f"(c[1]), "+f"(c[2]), "+f"(c[3])
        : "r"(a[0]), "r"(a[1]), "r"(a[2]), "r"(a[3]), "r"(b0), "r"(b1));
}

__device__ __forceinline__ uint32_t sw64(uint32_t b) { return b ^ ((b >> 3) & 0x30u); }
__device__ __forceinline__ uint32_t sw128(uint32_t b) { return b ^ ((b >> 3) & 0x70u); }

// ===========================================================================
// Device scratch
// ===========================================================================
__device__ __align__(256) __nv_bfloat16 g_xh[Mrows * Cn], g_xl[Mrows * Cn];
__device__ __align__(256) __nv_bfloat16 g_Wqkvth[3 * Cn * Cn], g_Wqkvtl[3 * Cn * Cn];
__device__ __align__(256) __nv_bfloat16 g_Wpth[Cn * Cn], g_Wptl[Cn * Cn];
__device__ __align__(256) __nv_bfloat16 g_W1th[FFn * Cn], g_W1tl[FFn * Cn];
__device__ __align__(256) __nv_bfloat16 g_W2th[Cn * FFn], g_W2tl[Cn * FFn];
__device__ __align__(256) float g_bqkv[3 * Cn];
__device__ __align__(256) __nv_bfloat16 g_qkvh[Mrows * 3 * Cn], g_qkvl[Mrows * 3 * Cn];
__device__ __align__(256) __nv_bfloat16 g_atth[Mrows * Cn], g_attl[Mrows * Cn];
__device__ __align__(256) __nv_bfloat16 g_hh[Mrows * Cn], g_hl[Mrows * Cn];
__device__ __align__(256) __nv_bfloat16 g_f1h[Mrows * FFn], g_f1l[Mrows * FFn];
__device__ __align__(256) float g_t0[Mrows * Cn];
__device__ __align__(256) float g_f2[Mrows * Cn];

// ===========================================================================
// Elementwise split: fp32 -> (hi, lo) bf16
// ===========================================================================
__global__ void split_kernel(const float* __restrict__ in, __nv_bfloat16* __restrict__ oh,
                             __nv_bfloat16* __restrict__ ol) {
    int i = blockIdx.x * 256 + threadIdx.x;
    float v = in[i];
    __nv_bfloat16 h = __float2bfloat16(v);
    oh[i] = h;
    ol[i] = __float2bfloat16(v - __bfloat162float(h));
}

// Concat qkv biases into one [3072] buffer
__global__ void bias_concat(const float* __restrict__ bq, const float* __restrict__ bk,
                            const float* __restrict__ bv, float* __restrict__ o) {
    int i = blockIdx.x * 256 + threadIdx.x;
    float v = (i < Cn) ? bq[i] : (i < 2 * Cn) ? bk[i - Cn] : bv[i - 2 * Cn];
    o[i] = v;
}

// ===========================================================================
// Tiled transpose+split
// ===========================================================================
__global__ void transpose_split(const float* __restrict__ in, __nv_bfloat16* __restrict__ oh,
                                __nv_bfloat16* __restrict__ ol, int R, int Cc) {
    __shared__ float tile[32][33];
    size_t boff = (size_t)blockIdx.z * R * Cc;
    const float* ip = in + boff;
    int i0 = blockIdx.y * 32, j0 = blockIdx.x * 32;
#pragma unroll
    for (int k = threadIdx.y; k < 32; k += 8)
        tile[k][threadIdx.x] = ip[(size_t)(i0 + k) * Cc + j0 + threadIdx.x];
    __syncthreads();
#pragma unroll
    for (int k = threadIdx.y; k < 32; k += 8) {
        float v = tile[threadIdx.x][k];
        __nv_bfloat16 h = __float2bfloat16(v);
        size_t o = boff + (size_t)(j0 + k) * R + i0 + threadIdx.x;
        oh[o] = h;
        ol[o] = __float2bfloat16(v - __bfloat162float(h));
    }
}

// ===========================================================================
// Tensor-core GEMM via mma.sync, bf16 hi/lo split (3-term fp32 emulation).
// CTA 128x128, 8 warps (4Mx2N), K-chunk 32, 3-stage cp.async, 2 CTAs/SM.
// ===========================================================================
#define STAGE_BYTES 32768
#define GEMM_SMEM (3 * STAGE_BYTES)

template <bool SPLIT, bool RELU>
__global__ void __launch_bounds__(256, 2)
gemm_mma(const __nv_bfloat16* __restrict__ Ahi, const __nv_bfloat16* __restrict__ Alo,
         const __nv_bfloat16* __restrict__ Bhi, const __nv_bfloat16* __restrict__ Blo,
         const float* __restrict__ bias,
         float* __restrict__ Cf, __nv_bfloat16* __restrict__ Chi, __nv_bfloat16* __restrict__ Clo,
         int M, int N, int K) {
    extern __shared__ char dsmem[];
    uint32_t sb = smem_u32(dsmem);

    int tid = threadIdx.x;
    int wid = tid >> 5;
    int lane = tid & 31;
    int n0 = blockIdx.x * 128;
    int m0 = blockIdx.y * 128;
    int wm = wid & 3;
    int wn = wid >> 2;

    const int NC = K >> 5;

    auto load_chunk = [&](int c, int stage) {
        uint32_t base = sb + (uint32_t)stage * STAGE_BYTES;
        size_t kof = (size_t)c * 32;
#pragma unroll
        for (int i = 0; i < 8; i++) {
            int g = i * 256 + tid;
            int tilei = g >> 9;
            int idx = g & 511;
            int row = idx >> 2;
            int ch = idx & 3;
            const __nv_bfloat16* src;
            if (tilei == 0)      src = Ahi + (size_t)(m0 + row) * K + kof + ch * 8;
            else if (tilei == 1) src = Alo + (size_t)(m0 + row) * K + kof + ch * 8;
            else if (tilei == 2) src = Bhi + (size_t)(n0 + row) * K + kof + ch * 8;
            else                 src = Blo + (size_t)(n0 + row) * K + kof + ch * 8;
            uint32_t dst = base + (uint32_t)tilei * 8192u + sw64((uint32_t)(row * 64 + ch * 16));
            CP_ASYNC16(dst, src);
        }
        CP_ASYNC_COMMIT();
    };

    float c[2][8][4];
#pragma unroll
    for (int mt = 0; mt < 2; mt++)
#pragma unroll
        for (int nt = 0; nt < 8; nt++)
#pragma unroll
            for (int j = 0; j < 4; j++) c[mt][nt][j] = 0.f;

    load_chunk(0, 0);
    load_chunk(1, 1);

    int arow = lane & 15;
    int aoff = (lane >> 4) * 16;
    int brow = ((lane >> 4) << 3) + (lane & 7);
    int boff = ((lane >> 3) & 1) * 16;

    for (int cc = 0; cc < NC; cc++) {
        if (cc == NC - 1) { CP_ASYNC_WAIT0(); } else { CP_ASYNC_WAIT1(); }
        __syncthreads();
        if (cc + 2 < NC) load_chunk(cc + 2, (cc + 2) % 3);

        uint32_t base = sb + (uint32_t)(cc % 3) * STAGE_BYTES;
#pragma unroll
        for (int k16 = 0; k16 < 2; k16++) {
            uint32_t ahi[2][4], alo[2][4];
#pragma unroll
            for (int mt = 0; mt < 2; mt++) {
                uint32_t byte = (uint32_t)((wm * 32 + mt * 16 + arow) * 64 + k16 * 32 + aoff);
                uint32_t sw = sw64(byte);
                ldsm4(ahi[mt], base + sw);
                ldsm4(alo[mt], base + 8192u + sw);
            }
#pragma unroll
            for (int nt16 = 0; nt16 < 4; nt16++) {
                uint32_t byte = (uint32_t)((wn * 64 + nt16 * 16 + brow) * 64 + k16 * 32 + boff);
                uint32_t sw = sw64(byte);
                uint32_t bh[4], bl[4];
                ldsm4(bh, base + 16384u + sw);
                ldsm4(bl, base + 24576u + sw);
                // term-major: 4 independent accumulators between same-acc reuse
#pragma unroll
                for (int term = 0; term < 3; term++) {
#pragma unroll
                    for (int half = 0; half < 2; half++) {
                        int nt = nt16 * 2 + half;
                        const uint32_t* aa = (term == 2) ? nullptr : nullptr;
#pragma unroll
                        for (int mt = 0; mt < 2; mt++) {
                            if (term == 0)      mma16816(c[mt][nt], ahi[mt], bh[half * 2], bh[half * 2 + 1]);
                            else if (term == 1) mma16816(c[mt][nt], ahi[mt], bl[half * 2], bl[half * 2 + 1]);
                            else                mma16816(c[mt][nt], alo[mt], bh[half * 2], bh[half * 2 + 1]);
                        }
                        (void)aa;
                    }
                }
            }
        }
    }

    int mbase = m0 + wm * 32;
    int nbase = n0 + wn * 64;
#pragma unroll
    for (int mt = 0; mt < 2; mt++) {
#pragma unroll
        for (int nt = 0; nt < 8; nt++) {
            int row0 = mbase + mt * 16 + (lane >> 2);
            int col = nbase + nt * 8 + (lane & 3) * 2;
            float b0 = bias[col], b1 = bias[col + 1];
#pragma unroll
            for (int half = 0; half < 2; half++) {
                int row = row0 + half * 8;
                float v0 = c[mt][nt][half * 2 + 0] + b0;
                float v1 = c[mt][nt][half * 2 + 1] + b1;
                if (RELU) { v0 = fmaxf(v0, 0.f); v1 = fmaxf(v1, 0.f); }
                if (SPLIT) {
                    __nv_bfloat16 h0 = __float2bfloat16(v0);
                    __nv_bfloat16 h1 = __float2bfloat16(v1);
                    __nv_bfloat162 hp; hp.x = h0; hp.y = h1;
                    __nv_bfloat162 lp;
                    lp.x = __float2bfloat16(v0 - __bfloat162float(h0));
                    lp.y = __float2bfloat16(v1 - __bfloat162float(h1));
                    *(__nv_bfloat162*)&Chi[(size_t)row * N + col] = hp;
                    *(__nv_bfloat162*)&Clo[(size_t)row * N + col] = lp;
                } else {
                    float2 r; r.x = v0; r.y = v1;
                    *(float2*)&Cf[(size_t)row * N + col] = r;
                }
            }
        }
    }
}

// ===========================================================================
// Tensor-core flash attention, bf16 split emulation, DOUBLE-BUFFERED KV.
// SMEM: Q 32KB | stage0 KV 32KB | stage1 KV 32KB = 96KB (2 CTAs/SM).
// ===========================================================================
#define ATT_SMEM 98304

__global__ void __launch_bounds__(256, 2) attn_mma(
    const __nv_bfloat16* __restrict__ QKVh, const __nv_bfloat16* __restrict__ QKVl,
    __nv_bfloat16* __restrict__ Oh, __nv_bfloat16* __restrict__ Ol) {
    extern __shared__ char dsmem[];
    uint32_t sbQ = smem_u32(dsmem);
    uint32_t sbKV = sbQ + 32768u;   // stage s at sbKV + s*32768: Kh|Kl|Vh|Vl 8KB each

    int tid = threadIdx.x;
    int wid = tid >> 5;
    int lane = tid & 31;
    int q0 = blockIdx.x * 128;
    int h = blockIdx.y;
    int b = blockIdx.z;

    const __nv_bfloat16* Qhg = QKVh + ((size_t)(b * Tn + q0)) * QKVS + h * HSn;
    const __nv_bfloat16* Qlg = QKVl + ((size_t)(b * Tn + q0)) * QKVS + h * HSn;
    const __nv_bfloat16* Khg = QKVh + ((size_t)(b * Tn)) * QKVS + Cn + h * HSn;
    const __nv_bfloat16* Klg = QKVl + ((size_t)(b * Tn)) * QKVS + Cn + h * HSn;
    const __nv_bfloat16* Vhg = QKVh + ((size_t)(b * Tn)) * QKVS + 2 * Cn + h * HSn;
    const __nv_bfloat16* Vlg = QKVl + ((size_t)(b * Tn)) * QKVS + 2 * Cn + h * HSn;

    auto load_kv = [&](int t) {
        int s0 = t * 64;
        uint32_t stb = sbKV + (uint32_t)(t & 1) * 32768u;
#pragma unroll
        for (int i = 0; i < 8; i++) {
            int g = i * 256 + tid;
            int mat = g >> 9;
            int idx = g & 511;
            int row = idx >> 3;
            int ch = idx & 7;
            const __nv_bfloat16* src;
            if (mat == 0)      src = Khg + (size_t)(s0 + row) * QKVS + ch * 8;
            else if (mat == 1) src = Klg + (size_t)(s0 + row) * QKVS + ch * 8;
            else if (mat == 2) src = Vhg + (size_t)(s0 + row) * QKVS + ch * 8;
            else               src = Vlg + (size_t)(s0 + row) * QKVS + ch * 8;
            CP_ASYNC16(stb + (uint32_t)mat * 8192u + sw128((uint32_t)(row * 128 + ch * 16)), src);
        }
        CP_ASYNC_COMMIT();
    };

    // Q (hi/lo) + first KV tile in one group
#pragma unroll
    for (int i = 0; i < 8; i++) {
        int g = i * 256 + tid;
        int hilo = g >> 10;
        int idx = g & 1023;
        int row = idx >> 3;
        int ch = idx & 7;
        const __nv_bfloat16* src = (hilo ? Qlg : Qhg) + (size_t)row * QKVS + ch * 8;
        CP_ASYNC16(sbQ + (uint32_t)hilo * 16384u + sw128((uint32_t)(row * 128 + ch * 16)), src);
    }
    {
        int s0 = 0;
        uint32_t stb = sbKV;
#pragma unroll
        for (int i = 0; i < 8; i++) {
            int g = i * 256 + tid;
            int mat = g >> 9;
            int idx = g & 511;
            int row = idx >> 3;
            int ch = idx & 7;
            const __nv_bfloat16* src;
            if (mat == 0)      src = Khg + (size_t)(s0 + row) * QKVS + ch * 8;
            else if (mat == 1) src = Klg + (size_t)(s0 + row) * QKVS + ch * 8;
            else if (mat == 2) src = Vhg + (size_t)(s0 + row) * QKVS + ch * 8;
            else               src = Vlg + (size_t)(s0 + row) * QKVS + ch * 8;
            CP_ASYNC16(stb + (uint32_t)mat * 8192u + sw128((uint32_t)(row * 128 + ch * 16)), src);
        }
        CP_ASYNC_COMMIT();
    }

    float m0s = NEG_BIG, m1s = NEG_BIG, l0 = 0.f, l1 = 0.f;
    float co[8][4];
#pragma unroll
    for (int nt = 0; nt < 8; nt++)
#pragma unroll
        for (int j = 0; j < 4; j++) co[nt][j] = 0.f;

    int rw = q0 + wid * 16;
    int r0 = rw + (lane >> 2);
    int nkt = q0 / 64 + 2;
    const float scale = 0.125f;

    int arow = lane & 15;
    int aoff = (lane >> 4) * 16;
    int brow = ((lane >> 4) << 3) + (lane & 7);
    int boff = ((lane >> 3) & 1) * 16;
    int vrow = ((lane >> 3) & 1) * 8 + (lane & 7);
    int vcol = (lane >> 4) * 8;

    for (int t = 0; t < nkt; t++) {
        // prev compute on stage (t+1)&1 finished by all warps -> safe to overwrite
        __syncthreads();
        if (t + 1 < nkt) { load_kv(t + 1); CP_ASYNC_WAIT1(); }
        else             { CP_ASYNC_WAIT0(); }
        __syncthreads();   // make stage t&1 visible to all warps

        int s0 = t * 64;
        uint32_t sbK = sbKV + (uint32_t)(t & 1) * 32768u;
        uint32_t sbV = sbK + 16384u;

        if (s0 <= rw + 15) {
            float sp[8][4];
#pragma unroll
            for (int nt = 0; nt < 8; nt++)
#pragma unroll
                for (int j = 0; j < 4; j++) sp[nt][j] = 0.f;

#pragma unroll
            for (int kk = 0; kk < 4; kk++) {
                uint32_t abyte = (uint32_t)((wid * 16 + arow) * 128 + kk * 32 + aoff);
                uint32_t aH[4], aL[4];
                ldsm4(aH, sbQ + sw128(abyte));
                ldsm4(aL, sbQ + 16384u + sw128(abyte));
#pragma unroll
                for (int nt16 = 0; nt16 < 4; nt16++) {
                    uint32_t bbyte = (uint32_t)((nt16 * 16 + brow) * 128 + kk * 32 + boff);
                    uint32_t bH[4], bL[4];
                    ldsm4(bH, sbK + sw128(bbyte));
                    ldsm4(bL, sbK + 8192u + sw128(bbyte));
#pragma unroll
                    for (int term = 0; term < 3; term++) {
#pragma unroll
                        for (int half = 0; half < 2; half++) {
                            int nt = nt16 * 2 + half;
                            if (term == 0)      mma16816(sp[nt], aH, bH[half * 2], bH[half * 2 + 1]);
                            else if (term == 1) mma16816(sp[nt], aH, bL[half * 2], bL[half * 2 + 1]);
                            else                mma16816(sp[nt], aL, bH[half * 2], bH[half * 2 + 1]);
                        }
                    }
                }
            }

            bool diag = (s0 + 63 > rw);
            float mx0 = NEG_BIG, mx1 = NEG_BIG;
#pragma unroll
            for (int nt = 0; nt < 8; nt++) {
                float c0 = sp[nt][0] * scale;
                float c1 = sp[nt][1] * scale;
                float c2 = sp[nt][2] * scale;
                float c3 = sp[nt][3] * scale;
                if (diag) {
                    int cg = s0 + nt * 8 + (lane & 3) * 2;
                    if (cg > r0) c0 = NEG_BIG;
                    if (cg + 1 > r0) c1 = NEG_BIG;
                    if (cg > r0 + 8) c2 = NEG_BIG;
                    if (cg + 1 > r0 + 8) c3 = NEG_BIG;
                }
                sp[nt][0] = c0; sp[nt][1] = c1; sp[nt][2] = c2; sp[nt][3] = c3;
                mx0 = fmaxf(mx0, fmaxf(c0, c1));
                mx1 = fmaxf(mx1, fmaxf(c2, c3));
            }
            mx0 = fmaxf(mx0, __shfl_xor_sync(0xffffffffu, mx0, 1));
            mx0 = fmaxf(mx0, __shfl_xor_sync(0xffffffffu, mx0, 2));
            mx1 = fmaxf(mx1, __shfl_xor_sync(0xffffffffu, mx1, 1));
            mx1 = fmaxf(mx1, __shfl_xor_sync(0xffffffffu, mx1, 2));

            float mn0 = fmaxf(m0s, mx0), mn1 = fmaxf(m1s, mx1);
            float al0 = __expf(m0s - mn0), al1 = __expf(m1s - mn1);
            m0s = mn0; m1s = mn1;

            float ps0 = 0.f, ps1 = 0.f;
#pragma unroll
            for (int nt = 0; nt < 8; nt++) {
                float p0 = __expf(sp[nt][0] - mn0);
                float p1 = __expf(sp[nt][1] - mn0);
                float p2 = __expf(sp[nt][2] - mn1);
                float p3 = __expf(sp[nt][3] - mn1);
                ps0 += p0 + p1; ps1 += p2 + p3;
                sp[nt][0] = p0; sp[nt][1] = p1; sp[nt][2] = p2; sp[nt][3] = p3;
            }
            ps0 += __shfl_xor_sync(0xffffffffu, ps0, 1);
            ps0 += __shfl_xor_sync(0xffffffffu, ps0, 2);
            ps1 += __shfl_xor_sync(0xffffffffu, ps1, 1);
            ps1 += __shfl_xor_sync(0xffffffffu, ps1, 2);
            l0 = l0 * al0 + ps0;
            l1 = l1 * al1 + ps1;
#pragma unroll
            for (int nt = 0; nt < 8; nt++) {
                co[nt][0] *= al0; co[nt][1] *= al0;
                co[nt][2] *= al1; co[nt][3] *= al1;
            }

#pragma unroll
            for (int kk = 0; kk < 4; kk++) {
                uint32_t aPh[4], aPl[4];
#pragma unroll
                for (int q = 0; q < 2; q++) {
                    int nt = 2 * kk + q;
#pragma unroll
                    for (int rr = 0; rr < 2; rr++) {
                        float v0 = sp[nt][rr * 2 + 0];
                        float v1 = sp[nt][rr * 2 + 1];
                        __nv_bfloat162 hp = __floats2bfloat162_rn(v0, v1);
                        float r0f = v0 - __bfloat162float(hp.x);
                        float r1f = v1 - __bfloat162float(hp.y);
                        __nv_bfloat162 lp = __floats2bfloat162_rn(r0f, r1f);
                        aPh[q * 2 + rr] = *(uint32_t*)&hp;
                        aPl[q * 2 + rr] = *(uint32_t*)&lp;
                    }
                }
#pragma unroll
                for (int dnt16 = 0; dnt16 < 4; dnt16++) {
                    uint32_t vbyte = (uint32_t)((kk * 16 + vrow) * 128 + (dnt16 * 16 + vcol) * 2);
                    uint32_t vH[4], vL[4];
                    ldsm4t(vH, sbV + sw128(vbyte));
                    ldsm4t(vL, sbV + 8192u + sw128(vbyte));
#pragma unroll
                    for (int term = 0; term < 3; term++) {
#pragma unroll
                        for (int half = 0; half < 2; half++) {
                            int dn = dnt16 * 2 + half;
                            if (term == 0)      mma16816(co[dn], aPh, vH[half * 2], vH[half * 2 + 1]);
                            else if (term == 1) mma16816(co[dn], aPh, vL[half * 2], vL[half * 2 + 1]);
                            else                mma16816(co[dn], aPl, vH[half * 2], vH[half * 2 + 1]);
                        }
                    }
                }
            }
        }
    }

    float inv0 = 1.f / l0, inv1 = 1.f / l1;
#pragma unroll
    for (int dn = 0; dn < 8; dn++) {
        int d = h * HSn + dn * 8 + (lane & 3) * 2;
#pragma unroll
        for (int half = 0; half < 2; half++) {
            int row = r0 + half * 8;
            float inv = half ? inv1 : inv0;
            float v0 = co[dn][half * 2 + 0] * inv;
            float v1 = co[dn][half * 2 + 1] * inv;
            __nv_bfloat162 hp = __floats2bfloat162_rn(v0, v1);
            __nv_bfloat162 lp = __floats2bfloat162_rn(v0 - __bfloat162float(hp.x),
                                                      v1 - __bfloat162float(hp.y));
            size_t base = ((size_t)(b * Tn + row)) * Cn + d;
            *(__nv_bfloat162*)&Oh[base] = hp;
            *(__nv_bfloat162*)&Ol[base] = lp;
        }
    }
}

// ===========================================================================
// LayerNorm
// ===========================================================================
template <bool SPLIT>
__global__ void ln_kernel(const float* __restrict__ X, const float* __restrict__ g,
                          const float* __restrict__ be, float* __restrict__ Y,
                          __nv_bfloat16* __restrict__ Yh, __nv_bfloat16* __restrict__ Yl) {
    int row = blockIdx.x;
    int tid = threadIdx.x;
    const float* xr = X + (size_t)row * Cn;

    float v[4];
    float s = 0.f, ss = 0.f;
#pragma unroll
    for (int i = 0; i < 4; i++) {
        v[i] = xr[tid + i * 256];
        s += v[i];
        ss += v[i] * v[i];
    }

    __shared__ float rs[256], rss[256];
    rs[tid] = s;
    rss[tid] = ss;
    __syncthreads();
    for (int off = 128; off; off >>= 1) {
        if (tid < off) {
            rs[tid] += rs[tid + off];
            rss[tid] += rss[tid + off];
        }
        __syncthreads();
    }
    float mean = rs[0] * (1.f / Cn);
    float var = rss[0] * (1.f / Cn) - mean * mean;
    float rstd = rsqrtf(var + EPSn);

#pragma unroll
    for (int i = 0; i < 4; i++) {
        int ccol = tid + i * 256;
        float y = (v[i] - mean) * rstd * g[ccol] + be[ccol];
        if (SPLIT) {
            __nv_bfloat16 hh = __float2bfloat16(y);
            Yh[(size_t)row * Cn + ccol] = hh;
            Yl[(size_t)row * Cn + ccol] = __float2bfloat16(y - __bfloat162float(hh));
        } else {
            Y[(size_t)row * Cn + ccol] = y;
        }
    }
}

// ===========================================================================
// Launch
// ===========================================================================
static float* symaddrf(const void* sym) {
    void* p = nullptr;
    cudaGetSymbolAddress(&p, sym);
    return (float*)p;
}
static __nv_bfloat16* symaddrb(const void* sym) {
    void* p = nullptr;
    cudaGetSymbolAddress(&p, sym);
    return (__nv_bfloat16*)p;
}

extern "C" void kernel_launch(void* const* d_in, const int* in_sizes, int n_in,
                              void* d_out, int out_size) {
    const float* x   = (const float*)d_in[0];
    const float* Wq  = (const float*)d_in[1];
    const float* bq  = (const float*)d_in[2];
    const float* Wk  = (const float*)d_in[3];
    const float* bk  = (const float*)d_in[4];
    const float* Wv  = (const float*)d_in[5];
    const float* bv  = (const float*)d_in[6];
    const float* Wp  = (const float*)d_in[7];
    const float* bp  = (const float*)d_in[8];
    const float* W1  = (const float*)d_in[9];
    const float* b1  = (const float*)d_in[10];
    const float* W2  = (const float*)d_in[11];
    const float* b2  = (const float*)d_in[12];
    const float* g1  = (const float*)d_in[13];
    const float* be1 = (const float*)d_in[14];
    const float* g2  = (const float*)d_in[15];
    const float* be2 = (const float*)d_in[16];
    float* out = (float*)d_out;

    __nv_bfloat16 *xh = symaddrb(g_xh), *xl = symaddrb(g_xl);
    __nv_bfloat16 *Wqkvth = symaddrb(g_Wqkvth), *Wqkvtl = symaddrb(g_Wqkvtl);
    __nv_bfloat16 *Wpth = symaddrb(g_Wpth), *Wptl = symaddrb(g_Wptl);
    __nv_bfloat16 *W1th = symaddrb(g_W1th), *W1tl = symaddrb(g_W1tl);
    __nv_bfloat16 *W2th = symaddrb(g_W2th), *W2tl = symaddrb(g_W2tl);
    __nv_bfloat16 *qkvh = symaddrb(g_qkvh), *qkvl = symaddrb(g_qkvl);
    __nv_bfloat16 *atth = symaddrb(g_atth), *attl = symaddrb(g_attl);
    __nv_bfloat16 *hh = symaddrb(g_hh), *hl = symaddrb(g_hl);
    __nv_bfloat16 *f1h = symaddrb(g_f1h), *f1l = symaddrb(g_f1l);
    float *bqkv = symaddrf(g_bqkv);
    float *t0 = symaddrf(g_t0), *f2 = symaddrf(g_f2);

    cudaFuncSetAttribute(gemm_mma<false, false>, cudaFuncAttributeMaxDynamicSharedMemorySize, GEMM_SMEM);
    cudaFuncSetAttribute(gemm_mma<true, false>,  cudaFuncAttributeMaxDynamicSharedMemorySize, GEMM_SMEM);
    cudaFuncSetAttribute(gemm_mma<true, true>,   cudaFuncAttributeMaxDynamicSharedMemorySize, GEMM_SMEM);
    cudaFuncSetAttribute(gemm_mma<false, true>,  cudaFuncAttributeMaxDynamicSharedMemorySize, GEMM_SMEM);
    cudaFuncSetAttribute(attn_mma, cudaFuncAttributeMaxDynamicSharedMemorySize, ATT_SMEM);

    const int M = Mrows;
    dim3 tb(32, 8);

    // 1) split x; transpose+split weights; concat qkv bias
    split_kernel<<<(M * Cn) / 256, 256>>>(x, xh, xl);
    transpose_split<<<dim3(HSn / 32, Cn / 32, Hn), tb>>>(Wq, Wqkvth, Wqkvtl, Cn, HSn);
    transpose_split<<<dim3(HSn / 32, Cn / 32, Hn), tb>>>(Wk, Wqkvth + Cn * Cn, Wqkvtl + Cn * Cn, Cn, HSn);
    transpose_split<<<dim3(HSn / 32, Cn / 32, Hn), tb>>>(Wv, Wqkvth + 2 * Cn * Cn, Wqkvtl + 2 * Cn * Cn, Cn, HSn);
    transpose_split<<<dim3(Cn / 32, Cn / 32, 1), tb>>>(Wp, Wpth, Wptl, Cn, Cn);
    transpose_split<<<dim3(FFn / 32, Cn / 32, 1), tb>>>(W1, W1th, W1tl, Cn, FFn);
    transpose_split<<<dim3(Cn / 32, FFn / 32, 1), tb>>>(W2, W2th, W2tl, FFn, Cn);
    bias_concat<<<(3 * Cn) / 256, 256>>>(bq, bk, bv, bqkv);

    // 2) fused QKV projection
    gemm_mma<true, false><<<dim3(3 * Cn / 128, M / 128), 256, GEMM_SMEM>>>(
        xh, xl, Wqkvth, Wqkvtl, bqkv, nullptr, qkvh, qkvl, M, 3 * Cn, Cn);

    // 3) tensor-core flash attention (double-buffered KV)
    attn_mma<<<dim3(Tn / 128, Hn, Bn), 256, ATT_SMEM>>>(qkvh, qkvl, atth, attl);

    // 4) output projection
    gemm_mma<false, false><<<dim3(Cn / 128, M / 128), 256, GEMM_SMEM>>>(
        atth, attl, Wpth, Wptl, bp, t0, nullptr, nullptr, M, Cn, Cn);

    // 5) LN1 -> split
    ln_kernel<true><<<M, 256>>>(t0, g1, be1, nullptr, hh, hl);

    // 6) FFN
    gemm_mma<true, true><<<dim3(FFn / 128, M / 128), 256, GEMM_SMEM>>>(
        hh, hl, W1th, W1tl, b1, nullptr, f1h, f1l, M, FFn, Cn);
    gemm_mma<false, true><<<dim3(Cn / 128, M / 128), 256, GEMM_SMEM>>>(
        f1h, f1l, W2th, W2tl, b2, f2, nullptr, nullptr, M, Cn, FFn);

    // 7) LN2 -> output
    ln_kernel<false><<<M, 256>>>(f2, g2, be2, out, nullptr, nullptr);
}